// round 1
// baseline (speedup 1.0000x reference)
#include <cuda_runtime.h>
#include <math.h>

#define B_   2
#define T_   2048
#define C_   1024
#define H_   16
#define HD_  64
#define NTOK (B_*T_)   // 4096

// Scratch (allocation-free rule: __device__ globals)
__device__ float g_q[B_*H_*T_*HD_];
__device__ float g_k[B_*H_*T_*HD_];
__device__ float g_v[B_*H_*T_*HD_];
__device__ float g_y[B_*T_*C_];

// ---------------------------------------------------------------------------
// GEMM: out[m][n] = sum_k A[m][k] * W[n][k] + bias[n]
// A: [4096,1024] row-major, W: [1024,1024] row-major (NT — both K-contiguous)
// BM=BN=64, BK=32, 256 threads, 4x4 microtile per thread.
// SPLIT_HEADS: write out in [B,H,T,HD] layout instead of [M,N].
// ---------------------------------------------------------------------------
template<bool SPLIT_HEADS>
__global__ void __launch_bounds__(256)
gemm_nt(const float* __restrict__ A, const float* __restrict__ W,
        const float* __restrict__ bias, float* __restrict__ out)
{
    const int BK = 32;
    __shared__ __align__(16) float As[BK][68];   // As[k][m]
    __shared__ __align__(16) float Bs[BK][68];   // Bs[k][n]

    int tid = threadIdx.x;
    int tx = tid & 15;        // n dim
    int ty = tid >> 4;        // m dim
    int m0 = blockIdx.y * 64;
    int n0 = blockIdx.x * 64;

    float acc[4][4];
    #pragma unroll
    for (int i = 0; i < 4; i++)
        #pragma unroll
        for (int j = 0; j < 4; j++) acc[i][j] = 0.f;

    for (int k0 = 0; k0 < C_; k0 += BK) {
        // load 64x32 A tile + 64x32 W tile, transposed into smem
        #pragma unroll
        for (int it = 0; it < 2; it++) {
            int f  = tid + it * 256;        // 0..511
            int r  = f >> 3;                // row within tile (0..63)
            int kc = f & 7;                 // float4 index along k (0..7)
            float4 a = *(const float4*)&A[(size_t)(m0 + r) * C_ + k0 + kc * 4];
            As[kc*4+0][r] = a.x; As[kc*4+1][r] = a.y;
            As[kc*4+2][r] = a.z; As[kc*4+3][r] = a.w;
            float4 b = *(const float4*)&W[(size_t)(n0 + r) * C_ + k0 + kc * 4];
            Bs[kc*4+0][r] = b.x; Bs[kc*4+1][r] = b.y;
            Bs[kc*4+2][r] = b.z; Bs[kc*4+3][r] = b.w;
        }
        __syncthreads();

        #pragma unroll
        for (int k = 0; k < BK; k++) {
            float4 ra4 = *(const float4*)&As[k][ty * 4];
            float4 rb4 = *(const float4*)&Bs[k][tx * 4];
            float ra[4] = {ra4.x, ra4.y, ra4.z, ra4.w};
            float rb[4] = {rb4.x, rb4.y, rb4.z, rb4.w};
            #pragma unroll
            for (int i = 0; i < 4; i++)
                #pragma unroll
                for (int j = 0; j < 4; j++)
                    acc[i][j] = fmaf(ra[i], rb[j], acc[i][j]);
        }
        __syncthreads();
    }

    #pragma unroll
    for (int i = 0; i < 4; i++) {
        int m = m0 + ty * 4 + i;
        #pragma unroll
        for (int j = 0; j < 4; j++) {
            int n = n0 + tx * 4 + j;
            float val = acc[i][j] + bias[n];
            if (SPLIT_HEADS) {
                int b = m / T_, t = m % T_;
                int h = n / HD_, d = n % HD_;
                g_dummy: ;
                ((float*)out)[(((size_t)b * H_ + h) * T_ + t) * HD_ + d] = val;
            } else {
                out[(size_t)m * C_ + n] = val;
            }
        }
    }
}

// ---------------------------------------------------------------------------
// Flash attention, fp32. One CTA per (bh, 64-query tile).
// S = (Q*scale) K^T and O += P V both as 64x64x64 smem GEMMs (4x4 microtiles).
// K smem tile is reused to hold transposed P between the two GEMMs.
// ---------------------------------------------------------------------------
__global__ void __launch_bounds__(256) attn_kernel()
{
    extern __shared__ float sm[];
    const int STR = 68;                       // padded row stride (float4-aligned)
    float* qs = sm;                           // qs[d][m]   (transposed)
    float* ks = sm + 64 * STR;                // ks[d][j] -> reused as Ps[j][m]
    float* vs = sm + 2 * 64 * STR;            // vs[j][d]   (natural)

    int tid = threadIdx.x;
    int tx  = tid & 15;                       // col group
    int ty  = tid >> 4;                       // row group
    int qb  = (T_/64 - 1) - blockIdx.x;       // heavy tiles first (causal imbalance)
    int bh  = blockIdx.y;

    const float* qptr = g_q + ((size_t)bh * T_ + qb * 64) * HD_;
    const float* kptr = g_k + (size_t)bh * T_ * HD_;
    const float* vptr = g_v + (size_t)bh * T_ * HD_;

    // load Q tile transposed, pre-scaled by 1/sqrt(64)
    #pragma unroll
    for (int it = 0; it < 4; it++) {
        int f  = tid + it * 256;              // 0..1023
        int r  = f >> 4;                      // 0..63
        int c4 = f & 15;                      // 0..15
        float4 v = *(const float4*)(qptr + (size_t)r * HD_ + c4 * 4);
        qs[(c4*4+0)*STR + r] = v.x * 0.125f;
        qs[(c4*4+1)*STR + r] = v.y * 0.125f;
        qs[(c4*4+2)*STR + r] = v.z * 0.125f;
        qs[(c4*4+3)*STR + r] = v.w * 0.125f;
    }

    float m_i[4], l_i[4], acc[4][4];
    #pragma unroll
    for (int i = 0; i < 4; i++) {
        m_i[i] = -1e30f; l_i[i] = 0.f;
        #pragma unroll
        for (int j = 0; j < 4; j++) acc[i][j] = 0.f;
    }

    for (int kb = 0; kb <= qb; kb++) {
        __syncthreads();   // protect ks(P)/vs from previous iteration readers

        // load K tile transposed + V tile natural
        #pragma unroll
        for (int it = 0; it < 4; it++) {
            int f  = tid + it * 256;
            int r  = f >> 4;
            int c4 = f & 15;
            float4 kv = *(const float4*)(kptr + ((size_t)(kb*64 + r)) * HD_ + c4 * 4);
            ks[(c4*4+0)*STR + r] = kv.x;
            ks[(c4*4+1)*STR + r] = kv.y;
            ks[(c4*4+2)*STR + r] = kv.z;
            ks[(c4*4+3)*STR + r] = kv.w;
            float4 vv = *(const float4*)(vptr + ((size_t)(kb*64 + r)) * HD_ + c4 * 4);
            *(float4*)(vs + r * STR + c4 * 4) = vv;
        }
        __syncthreads();

        // S = Q K^T  (64x64x64)
        float s[4][4];
        #pragma unroll
        for (int i = 0; i < 4; i++)
            #pragma unroll
            for (int j = 0; j < 4; j++) s[i][j] = 0.f;

        #pragma unroll
        for (int d = 0; d < 64; d++) {
            float4 ra = *(const float4*)(qs + d * STR + ty * 4);
            float4 rb = *(const float4*)(ks + d * STR + tx * 4);
            float qa[4] = {ra.x, ra.y, ra.z, ra.w};
            float kk[4] = {rb.x, rb.y, rb.z, rb.w};
            #pragma unroll
            for (int i = 0; i < 4; i++)
                #pragma unroll
                for (int j = 0; j < 4; j++)
                    s[i][j] = fmaf(qa[i], kk[j], s[i][j]);
        }

        // causal mask on diagonal block (local row/col compare — same base)
        if (kb == qb) {
            #pragma unroll
            for (int i = 0; i < 4; i++)
                #pragma unroll
                for (int j = 0; j < 4; j++)
                    if (tx * 4 + j > ty * 4 + i) s[i][j] = -1e30f;
        }

        __syncthreads();   // everyone done reading ks as K; will rewrite as P

        // online softmax (row stats reduced over 16 tx lanes via shuffles)
        #pragma unroll
        for (int i = 0; i < 4; i++) {
            float mx = fmaxf(fmaxf(s[i][0], s[i][1]), fmaxf(s[i][2], s[i][3]));
            #pragma unroll
            for (int off = 1; off < 16; off <<= 1)
                mx = fmaxf(mx, __shfl_xor_sync(0xffffffffu, mx, off));
            float newm = fmaxf(m_i[i], mx);
            float sum = 0.f;
            #pragma unroll
            for (int j = 0; j < 4; j++) {
                float p = __expf(s[i][j] - newm);
                s[i][j] = p;
                sum += p;
            }
            #pragma unroll
            for (int off = 1; off < 16; off <<= 1)
                sum += __shfl_xor_sync(0xffffffffu, sum, off);
            float corr = __expf(m_i[i] - newm);
            l_i[i] = l_i[i] * corr + sum;
            m_i[i] = newm;
            #pragma unroll
            for (int j = 0; j < 4; j++) acc[i][j] *= corr;
            // store P transposed: Ps[j][m] (into ks buffer)
            #pragma unroll
            for (int j = 0; j < 4; j++)
                ks[(tx*4 + j) * STR + (ty*4 + i)] = s[i][j];
        }
        __syncthreads();

        // O += P V  (64x64x64)
        #pragma unroll 8
        for (int j = 0; j < 64; j++) {
            float4 pa = *(const float4*)(ks + j * STR + ty * 4);
            float4 vb = *(const float4*)(vs + j * STR + tx * 4);
            float pp[4] = {pa.x, pa.y, pa.z, pa.w};
            float vv[4] = {vb.x, vb.y, vb.z, vb.w};
            #pragma unroll
            for (int i = 0; i < 4; i++)
                #pragma unroll
                for (int jj = 0; jj < 4; jj++)
                    acc[i][jj] = fmaf(pp[i], vv[jj], acc[i][jj]);
        }
    }

    // epilogue: O /= l, write y in [B,T,C] layout
    int b = bh >> 4;     // bh = b*H + h, H=16
    int h = bh & 15;
    #pragma unroll
    for (int i = 0; i < 4; i++) {
        float inv = 1.0f / l_i[i];
        int t = qb * 64 + ty * 4 + i;
        float* yrow = g_y + ((size_t)(b * T_ + t)) * C_ + h * HD_ + tx * 4;
        #pragma unroll
        for (int j = 0; j < 4; j++) yrow[j] = acc[i][j] * inv;
    }
}

// ---------------------------------------------------------------------------
extern "C" void kernel_launch(void* const* d_in, const int* in_sizes, int n_in,
                              void* d_out, int out_size)
{
    const float* x  = (const float*)d_in[0];
    const float* Wq = (const float*)d_in[1];
    const float* bq = (const float*)d_in[2];
    const float* Wk = (const float*)d_in[3];
    const float* bk = (const float*)d_in[4];
    const float* Wv = (const float*)d_in[5];
    const float* bv = (const float*)d_in[6];
    const float* Wp = (const float*)d_in[7];
    const float* bp = (const float*)d_in[8];
    float* out = (float*)d_out;

    float *qp, *kp, *vp, *yp;
    cudaGetSymbolAddress((void**)&qp, g_q);
    cudaGetSymbolAddress((void**)&kp, g_k);
    cudaGetSymbolAddress((void**)&vp, g_v);
    cudaGetSymbolAddress((void**)&yp, g_y);

    dim3 gemm_grid(C_ / 64, NTOK / 64);   // (16, 64)

    gemm_nt<true><<<gemm_grid, 256>>>(x, Wq, bq, qp);
    gemm_nt<true><<<gemm_grid, 256>>>(x, Wk, bk, kp);
    gemm_nt<true><<<gemm_grid, 256>>>(x, Wv, bv, vp);

    const int ATTN_SMEM = 3 * 64 * 68 * 4;   // 52224 bytes
    cudaFuncSetAttribute(attn_kernel, cudaFuncAttributeMaxDynamicSharedMemorySize, ATTN_SMEM);
    attn_kernel<<<dim3(T_ / 64, B_ * H_), 256, ATTN_SMEM>>>();

    gemm_nt<false><<<gemm_grid, 256>>>(yp, Wp, bp, out);
}

// round 3
// speedup vs baseline: 1.7133x; 1.7133x over previous
#include <cuda_runtime.h>
#include <cuda_fp16.h>
#include <math.h>
#include <stdint.h>

#define B_   2
#define T_   2048
#define C_   1024
#define H_   16
#define HD_  64
#define NTOK (B_*T_)   // 4096

// ---------------------------------------------------------------------------
// Scratch (__device__ globals; allocation-free rule)
// ---------------------------------------------------------------------------
__device__ float  g_q[B_*H_*T_*HD_];
__device__ float  g_k[B_*H_*T_*HD_];
__device__ float  g_v[B_*H_*T_*HD_];
__device__ float  g_y[B_*T_*C_];
__device__ __half g_xh[NTOK*C_];     // hi halves of x (later: of y)
__device__ __half g_xl[NTOK*C_];     // lo halves
__device__ __half g_wh[4*C_*C_];     // hi halves of Wq,Wk,Wv,Wp
__device__ __half g_wl[4*C_*C_];

// ---------------------------------------------------------------------------
// PTX helpers (all sm_80-baseline — no 'a'-gated instructions)
// ---------------------------------------------------------------------------
__device__ __forceinline__ uint32_t smem_u32(const void* p) {
    uint32_t a;
    asm("{ .reg .u64 t; cvta.to.shared.u64 t, %1; cvt.u32.u64 %0, t; }"
        : "=r"(a) : "l"(p));
    return a;
}

__device__ __forceinline__ void cp16(uint32_t dst, const void* src) {
    asm volatile("cp.async.ca.shared.global [%0], [%1], 16;"
                 :: "r"(dst), "l"(src));
}

#define CP_COMMIT()  asm volatile("cp.async.commit_group;" ::: "memory")
#define CP_WAIT(N)   asm volatile("cp.async.wait_group " #N ";" ::: "memory")

#define LDMX4(r, addr) \
    asm volatile("ldmatrix.sync.aligned.m8n8.x4.shared.b16 {%0,%1,%2,%3}, [%4];" \
        : "=r"((r)[0]), "=r"((r)[1]), "=r"((r)[2]), "=r"((r)[3]) : "r"(addr))

#define MMA16816(d, a, b) \
    asm volatile("mma.sync.aligned.m16n8k16.row.col.f32.f16.f16.f32 " \
        "{%0,%1,%2,%3}, {%4,%5,%6,%7}, {%8,%9}, {%0,%1,%2,%3};" \
        : "+f"((d)[0]), "+f"((d)[1]), "+f"((d)[2]), "+f"((d)[3]) \
        : "r"((a)[0]), "r"((a)[1]), "r"((a)[2]), "r"((a)[3]), \
          "r"((b)[0]), "r"((b)[1]))

// ---------------------------------------------------------------------------
// fp32 -> (hi fp16, lo fp16) split conversion, 4 elems/thread
// ---------------------------------------------------------------------------
__global__ void __launch_bounds__(256)
cvt_split(const float4* __restrict__ src, __half2* __restrict__ hi,
          __half2* __restrict__ lo, int n4)
{
    int i = blockIdx.x * blockDim.x + threadIdx.x;
    if (i >= n4) return;
    float4 f = src[i];
    __half2 h01 = __floats2half2_rn(f.x, f.y);
    __half2 h23 = __floats2half2_rn(f.z, f.w);
    float2 b01 = __half22float2(h01);
    float2 b23 = __half22float2(h23);
    __half2 l01 = __floats2half2_rn(f.x - b01.x, f.y - b01.y);
    __half2 l23 = __floats2half2_rn(f.z - b23.x, f.w - b23.y);
    hi[2*i]   = h01;  hi[2*i+1] = h23;
    lo[2*i]   = l01;  lo[2*i+1] = l23;
}

// ---------------------------------------------------------------------------
// HMMA GEMM: out[m][n] = sum_k A[m][k]*B[n][k] + bias[n], split-fp16 x3 MMA
// CTA tile 128x128, BK=64 halves (128B rows), 256 threads (8 warps, 2x4),
// warp tile 64x32, cp.async double buffer, XOR-swizzled smem.
// smem stage (64 KB): Ah[16K] Al[16K] Bh[16K] Bl[16K]; 2 stages = 128 KB.
// ---------------------------------------------------------------------------
#define GEMM_SMEM (2*65536)

__device__ __forceinline__ void load_stage(
    uint32_t sb,
    const __half* __restrict__ Ah, const __half* __restrict__ Al,
    const __half* __restrict__ Bh, const __half* __restrict__ Bl,
    int m0, int n0, int k0, int tid)
{
    #pragma unroll
    for (int i = 0; i < 4; i++) {
        int idx = tid + i * 256;                 // 0..1023 (128 rows x 8 units)
        int r = idx >> 3, u = idx & 7;
        uint32_t doff = r * 128 + (((u ^ (r & 7))) << 4);
        size_t aoff = (size_t)(m0 + r) * C_ + k0 + u * 8;
        size_t boff = (size_t)(n0 + r) * C_ + k0 + u * 8;
        cp16(sb +         doff, Ah + aoff);
        cp16(sb + 16384 + doff, Al + aoff);
        cp16(sb + 32768 + doff, Bh + boff);
        cp16(sb + 49152 + doff, Bl + boff);
    }
}

template<bool SPLIT>
__global__ void __launch_bounds__(256)
gemm_hmma(const __half* __restrict__ Ah, const __half* __restrict__ Al,
          const __half* __restrict__ Bh, const __half* __restrict__ Bl,
          const float* __restrict__ bias, float* __restrict__ out)
{
    extern __shared__ __align__(1024) char smem[];
    uint32_t sbase = smem_u32(smem);
    const int tid  = threadIdx.x;
    const int lane = tid & 31;
    const int warp = tid >> 5;
    const int wm   = warp >> 2;       // 0..1  -> m offset wm*64
    const int wn   = warp & 3;        // 0..3  -> n offset wn*32
    const int m0   = blockIdx.y * 128;
    const int n0   = blockIdx.x * 128;

    float acc[4][4][4];
    #pragma unroll
    for (int i = 0; i < 4; i++)
        #pragma unroll
        for (int j = 0; j < 4; j++)
            #pragma unroll
            for (int k = 0; k < 4; k++) acc[i][j][k] = 0.f;

    load_stage(sbase, Ah, Al, Bh, Bl, m0, n0, 0, tid);
    CP_COMMIT();

    for (int kt = 0; kt < 16; kt++) {
        if (kt + 1 < 16) {
            load_stage(sbase + ((kt + 1) & 1) * 65536, Ah, Al, Bh, Bl,
                       m0, n0, (kt + 1) * 64, tid);
            CP_COMMIT();
            CP_WAIT(1);
        } else {
            CP_WAIT(0);
        }
        __syncthreads();

        uint32_t sb = sbase + (kt & 1) * 65536;

        #pragma unroll
        for (int ks = 0; ks < 4; ks++) {
            // --- A fragments (hi & lo), 4 m16 tiles ---
            uint32_t ah[4][4], al[4][4];
            {
                int arow = wm * 64 + (lane & 15);
                int aku  = ks * 2 + (lane >> 4);
                #pragma unroll
                for (int mi = 0; mi < 4; mi++) {
                    int r = arow + mi * 16;
                    uint32_t addr = sb + r * 128 + ((aku ^ (r & 7)) << 4);
                    LDMX4(ah[mi], addr);
                    LDMX4(al[mi], addr + 16384);
                }
            }
            // --- B fragments (hi & lo), 4 n8 tiles via 2x ldmatrix.x4 ---
            uint32_t bh[4][2], bl[4][2];
            {
                int brow0 = wn * 32 + ((lane >> 4) << 3) + (lane & 7);
                int bku   = ks * 2 + ((lane >> 3) & 1);
                #pragma unroll
                for (int nj2 = 0; nj2 < 2; nj2++) {
                    int r = brow0 + nj2 * 16;
                    uint32_t addr = sb + 32768 + r * 128 + ((bku ^ (r & 7)) << 4);
                    uint32_t t[4];
                    LDMX4(t, addr);
                    bh[2*nj2][0] = t[0]; bh[2*nj2][1] = t[1];
                    bh[2*nj2+1][0] = t[2]; bh[2*nj2+1][1] = t[3];
                    LDMX4(t, addr + 16384);
                    bl[2*nj2][0] = t[0]; bl[2*nj2][1] = t[1];
                    bl[2*nj2+1][0] = t[2]; bl[2*nj2+1][1] = t[3];
                }
            }
            // --- 3-term split MMAs ---
            #pragma unroll
            for (int mi = 0; mi < 4; mi++)
                #pragma unroll
                for (int nj = 0; nj < 4; nj++) {
                    MMA16816(acc[mi][nj], ah[mi], bh[nj]);
                    MMA16816(acc[mi][nj], al[mi], bh[nj]);
                    MMA16816(acc[mi][nj], ah[mi], bl[nj]);
                }
        }
        __syncthreads();
    }

    // epilogue: bias add + (optional) head-split store, float2 per write
    const int r0 = lane >> 2;
    const int c0 = (lane & 3) * 2;
    #pragma unroll
    for (int mi = 0; mi < 4; mi++) {
        #pragma unroll
        for (int nj = 0; nj < 4; nj++) {
            int n = n0 + wn * 32 + nj * 8 + c0;
            float2 bv = *(const float2*)(bias + n);
            #pragma unroll
            for (int h2 = 0; h2 < 2; h2++) {
                int m = m0 + wm * 64 + mi * 16 + r0 + h2 * 8;
                float2 o;
                o.x = acc[mi][nj][h2*2+0] + bv.x;
                o.y = acc[mi][nj][h2*2+1] + bv.y;
                float* dst;
                if (SPLIT) {
                    int b = m >> 11, t = m & (T_ - 1);
                    int h = n >> 6,  d = n & 63;
                    dst = out + (((size_t)(b * H_ + h) * T_ + t) * HD_) + d;
                } else {
                    dst = out + (size_t)m * C_ + n;
                }
                *(float2*)dst = o;
            }
        }
    }
}

// ---------------------------------------------------------------------------
// Flash attention, fp32 SIMT (unchanged from R1: ~70% of fp32 roofline)
// ---------------------------------------------------------------------------
__global__ void __launch_bounds__(256) attn_kernel()
{
    extern __shared__ float sm[];
    const int STR = 68;
    float* qs = sm;                 // qs[d][m] transposed
    float* ks = sm + 64 * STR;      // ks[d][j] -> reused as Ps[j][m]
    float* vs = sm + 2 * 64 * STR;  // vs[j][d]

    int tid = threadIdx.x;
    int tx  = tid & 15;
    int ty  = tid >> 4;
    int qb  = (T_/64 - 1) - blockIdx.x;   // heavy tiles first
    int bh  = blockIdx.y;

    const float* qptr = g_q + ((size_t)bh * T_ + qb * 64) * HD_;
    const float* kptr = g_k + (size_t)bh * T_ * HD_;
    const float* vptr = g_v + (size_t)bh * T_ * HD_;

    #pragma unroll
    for (int it = 0; it < 4; it++) {
        int f  = tid + it * 256;
        int r  = f >> 4;
        int c4 = f & 15;
        float4 v = *(const float4*)(qptr + (size_t)r * HD_ + c4 * 4);
        qs[(c4*4+0)*STR + r] = v.x * 0.125f;
        qs[(c4*4+1)*STR + r] = v.y * 0.125f;
        qs[(c4*4+2)*STR + r] = v.z * 0.125f;
        qs[(c4*4+3)*STR + r] = v.w * 0.125f;
    }

    float m_i[4], l_i[4], acc[4][4];
    #pragma unroll
    for (int i = 0; i < 4; i++) {
        m_i[i] = -1e30f; l_i[i] = 0.f;
        #pragma unroll
        for (int j = 0; j < 4; j++) acc[i][j] = 0.f;
    }

    for (int kb = 0; kb <= qb; kb++) {
        __syncthreads();
        #pragma unroll
        for (int it = 0; it < 4; it++) {
            int f  = tid + it * 256;
            int r  = f >> 4;
            int c4 = f & 15;
            float4 kv = *(const float4*)(kptr + ((size_t)(kb*64 + r)) * HD_ + c4 * 4);
            ks[(c4*4+0)*STR + r] = kv.x;
            ks[(c4*4+1)*STR + r] = kv.y;
            ks[(c4*4+2)*STR + r] = kv.z;
            ks[(c4*4+3)*STR + r] = kv.w;
            float4 vv = *(const float4*)(vptr + ((size_t)(kb*64 + r)) * HD_ + c4 * 4);
            *(float4*)(vs + r * STR + c4 * 4) = vv;
        }
        __syncthreads();

        float s[4][4];
        #pragma unroll
        for (int i = 0; i < 4; i++)
            #pragma unroll
            for (int j = 0; j < 4; j++) s[i][j] = 0.f;

        #pragma unroll
        for (int d = 0; d < 64; d++) {
            float4 ra = *(const float4*)(qs + d * STR + ty * 4);
            float4 rb = *(const float4*)(ks + d * STR + tx * 4);
            float qa[4] = {ra.x, ra.y, ra.z, ra.w};
            float kk[4] = {rb.x, rb.y, rb.z, rb.w};
            #pragma unroll
            for (int i = 0; i < 4; i++)
                #pragma unroll
                for (int j = 0; j < 4; j++)
                    s[i][j] = fmaf(qa[i], kk[j], s[i][j]);
        }

        if (kb == qb) {
            #pragma unroll
            for (int i = 0; i < 4; i++)
                #pragma unroll
                for (int j = 0; j < 4; j++)
                    if (tx * 4 + j > ty * 4 + i) s[i][j] = -1e30f;
        }

        __syncthreads();

        #pragma unroll
        for (int i = 0; i < 4; i++) {
            float mx = fmaxf(fmaxf(s[i][0], s[i][1]), fmaxf(s[i][2], s[i][3]));
            #pragma unroll
            for (int off = 1; off < 16; off <<= 1)
                mx = fmaxf(mx, __shfl_xor_sync(0xffffffffu, mx, off));
            float newm = fmaxf(m_i[i], mx);
            float sum = 0.f;
            #pragma unroll
            for (int j = 0; j < 4; j++) {
                float p = __expf(s[i][j] - newm);
                s[i][j] = p;
                sum += p;
            }
            #pragma unroll
            for (int off = 1; off < 16; off <<= 1)
                sum += __shfl_xor_sync(0xffffffffu, sum, off);
            float corr = __expf(m_i[i] - newm);
            l_i[i] = l_i[i] * corr + sum;
            m_i[i] = newm;
            #pragma unroll
            for (int j = 0; j < 4; j++) acc[i][j] *= corr;
            #pragma unroll
            for (int j = 0; j < 4; j++)
                ks[(tx*4 + j) * STR + (ty*4 + i)] = s[i][j];
        }
        __syncthreads();

        #pragma unroll 8
        for (int j = 0; j < 64; j++) {
            float4 pa = *(const float4*)(ks + j * STR + ty * 4);
            float4 vb = *(const float4*)(vs + j * STR + tx * 4);
            float pp[4] = {pa.x, pa.y, pa.z, pa.w};
            float vv[4] = {vb.x, vb.y, vb.z, vb.w};
            #pragma unroll
            for (int i = 0; i < 4; i++)
                #pragma unroll
                for (int jj = 0; jj < 4; jj++)
                    acc[i][jj] = fmaf(pp[i], vv[jj], acc[i][jj]);
        }
    }

    int b = bh >> 4;
    int h = bh & 15;
    #pragma unroll
    for (int i = 0; i < 4; i++) {
        float inv = 1.0f / l_i[i];
        int t = qb * 64 + ty * 4 + i;
        float* yrow = g_y + ((size_t)(b * T_ + t)) * C_ + h * HD_ + tx * 4;
        #pragma unroll
        for (int j = 0; j < 4; j++) yrow[j] = acc[i][j] * inv;
    }
}

// ---------------------------------------------------------------------------
extern "C" void kernel_launch(void* const* d_in, const int* in_sizes, int n_in,
                              void* d_out, int out_size)
{
    const float* x  = (const float*)d_in[0];
    const float* Wq = (const float*)d_in[1];
    const float* bq = (const float*)d_in[2];
    const float* Wk = (const float*)d_in[3];
    const float* bk = (const float*)d_in[4];
    const float* Wv = (const float*)d_in[5];
    const float* bv = (const float*)d_in[6];
    const float* Wp = (const float*)d_in[7];
    const float* bp = (const float*)d_in[8];
    float* out = (float*)d_out;

    float *qp, *kp, *vp, *yp;
    __half *xh, *xl, *wh, *wl;
    cudaGetSymbolAddress((void**)&qp, g_q);
    cudaGetSymbolAddress((void**)&kp, g_k);
    cudaGetSymbolAddress((void**)&vp, g_v);
    cudaGetSymbolAddress((void**)&yp, g_y);
    cudaGetSymbolAddress((void**)&xh, g_xh);
    cudaGetSymbolAddress((void**)&xl, g_xl);
    cudaGetSymbolAddress((void**)&wh, g_wh);
    cudaGetSymbolAddress((void**)&wl, g_wl);

    cudaFuncSetAttribute(gemm_hmma<true>,  cudaFuncAttributeMaxDynamicSharedMemorySize, GEMM_SMEM);
    cudaFuncSetAttribute(gemm_hmma<false>, cudaFuncAttributeMaxDynamicSharedMemorySize, GEMM_SMEM);
    const int ATTN_SMEM = 3 * 64 * 68 * 4;
    cudaFuncSetAttribute(attn_kernel, cudaFuncAttributeMaxDynamicSharedMemorySize, ATTN_SMEM);

    // split-convert x and the 4 weight matrices to fp16 hi/lo
    const int NX4 = NTOK * C_ / 4;     // 1M
    const int NW4 = C_ * C_ / 4;       // 256K
    cvt_split<<<(NX4 + 255)/256, 256>>>((const float4*)x,  (__half2*)xh, (__half2*)xl, NX4);
    cvt_split<<<(NW4 + 255)/256, 256>>>((const float4*)Wq, (__half2*)(wh + 0*(size_t)C_*C_), (__half2*)(wl + 0*(size_t)C_*C_), NW4);
    cvt_split<<<(NW4 + 255)/256, 256>>>((const float4*)Wk, (__half2*)(wh + 1*(size_t)C_*C_), (__half2*)(wl + 1*(size_t)C_*C_), NW4);
    cvt_split<<<(NW4 + 255)/256, 256>>>((const float4*)Wv, (__half2*)(wh + 2*(size_t)C_*C_), (__half2*)(wl + 2*(size_t)C_*C_), NW4);
    cvt_split<<<(NW4 + 255)/256, 256>>>((const float4*)Wp, (__half2*)(wh + 3*(size_t)C_*C_), (__half2*)(wl + 3*(size_t)C_*C_), NW4);

    dim3 ggrid(C_/128, NTOK/128);   // (8, 32)
    gemm_hmma<true><<<ggrid, 256, GEMM_SMEM>>>(xh, xl, wh + 0*(size_t)C_*C_, wl + 0*(size_t)C_*C_, bq, qp);
    gemm_hmma<true><<<ggrid, 256, GEMM_SMEM>>>(xh, xl, wh + 1*(size_t)C_*C_, wl + 1*(size_t)C_*C_, bk, kp);
    gemm_hmma<true><<<ggrid, 256, GEMM_SMEM>>>(xh, xl, wh + 2*(size_t)C_*C_, wl + 2*(size_t)C_*C_, bv, vp);

    attn_kernel<<<dim3(T_/64, B_*H_), 256, ATTN_SMEM>>>();

    // out-projection: convert y, reuse x hi/lo buffers
    cvt_split<<<(NX4 + 255)/256, 256>>>((const float4*)yp, (__half2*)xh, (__half2*)xl, NX4);
    gemm_hmma<false><<<ggrid, 256, GEMM_SMEM>>>(xh, xl, wh + 3*(size_t)C_*C_, wl + 3*(size_t)C_*C_, bp, out);
}

// round 4
// speedup vs baseline: 3.3826x; 1.9743x over previous
#include <cuda_runtime.h>
#include <cuda_fp16.h>
#include <math.h>
#include <stdint.h>

#define B_   2
#define T_   2048
#define C_   1024
#define H_   16
#define HD_  64
#define NTOK (B_*T_)   // 4096

// ---------------------------------------------------------------------------
// Scratch (__device__ globals; allocation-free rule)
// ---------------------------------------------------------------------------
__device__ __half g_qh[NTOK*C_], g_ql[NTOK*C_];
__device__ __half g_kh[NTOK*C_], g_kl[NTOK*C_];
__device__ __half g_vh[NTOK*C_], g_vl[NTOK*C_];
__device__ __half g_xh[NTOK*C_], g_xl[NTOK*C_];   // x hi/lo, later y hi/lo
__device__ __half g_wh[4*C_*C_], g_wl[4*C_*C_];

// ---------------------------------------------------------------------------
// PTX helpers (sm_80-baseline only — harness compiles for sm_103 w/o 'a')
// ---------------------------------------------------------------------------
__device__ __forceinline__ uint32_t smem_u32(const void* p) {
    uint32_t a;
    asm("{ .reg .u64 t; cvta.to.shared.u64 t, %1; cvt.u32.u64 %0, t; }"
        : "=r"(a) : "l"(p));
    return a;
}
__device__ __forceinline__ void cp16(uint32_t dst, const void* src) {
    asm volatile("cp.async.ca.shared.global [%0], [%1], 16;" :: "r"(dst), "l"(src));
}
#define CP_COMMIT()  asm volatile("cp.async.commit_group;" ::: "memory")
#define CP_WAIT(N)   asm volatile("cp.async.wait_group " #N ";" ::: "memory")

#define LDMX4(r, addr) \
    asm volatile("ldmatrix.sync.aligned.m8n8.x4.shared.b16 {%0,%1,%2,%3}, [%4];" \
        : "=r"((r)[0]), "=r"((r)[1]), "=r"((r)[2]), "=r"((r)[3]) : "r"(addr))
#define LDMX4T(r, addr) \
    asm volatile("ldmatrix.sync.aligned.m8n8.x4.trans.shared.b16 {%0,%1,%2,%3}, [%4];" \
        : "=r"((r)[0]), "=r"((r)[1]), "=r"((r)[2]), "=r"((r)[3]) : "r"(addr))

#define MMA16816(d, a, b) \
    asm volatile("mma.sync.aligned.m16n8k16.row.col.f32.f16.f16.f32 " \
        "{%0,%1,%2,%3}, {%4,%5,%6,%7}, {%8,%9}, {%0,%1,%2,%3};" \
        : "+f"((d)[0]), "+f"((d)[1]), "+f"((d)[2]), "+f"((d)[3]) \
        : "r"((a)[0]), "r"((a)[1]), "r"((a)[2]), "r"((a)[3]), \
          "r"((b)[0]), "r"((b)[1]))

__device__ __forceinline__ float ex2(float x) {
    float r;
    asm("ex2.approx.ftz.f32 %0, %1;" : "=f"(r) : "f"(x));
    return r;
}
__device__ __forceinline__ uint32_t packh2(float a, float b) {
    __half2 h = __floats2half2_rn(a, b);
    return *reinterpret_cast<uint32_t*>(&h);
}

// ---------------------------------------------------------------------------
// fp32 -> (hi fp16, lo fp16) split conversion
// ---------------------------------------------------------------------------
__global__ void __launch_bounds__(256)
cvt_split(const float4* __restrict__ src, __half2* __restrict__ hi,
          __half2* __restrict__ lo, int n4)
{
    int i = blockIdx.x * blockDim.x + threadIdx.x;
    if (i >= n4) return;
    float4 f = src[i];
    __half2 h01 = __floats2half2_rn(f.x, f.y);
    __half2 h23 = __floats2half2_rn(f.z, f.w);
    float2 b01 = __half22float2(h01);
    float2 b23 = __half22float2(h23);
    hi[2*i]   = h01;  hi[2*i+1] = h23;
    lo[2*i]   = __floats2half2_rn(f.x - b01.x, f.y - b01.y);
    lo[2*i+1] = __floats2half2_rn(f.z - b23.x, f.w - b23.y);
}

// ---------------------------------------------------------------------------
// HMMA GEMM: out[m][n] = sum_k A[m][k]*B[n][k] + bias[n], split-fp16 x3 MMA
// MODE 0: fp32 out [m][n].  MODE 1: half hi/lo out, [B,H,T,64], pre-scaled.
// ---------------------------------------------------------------------------
#define GEMM_SMEM (2*65536)

__device__ __forceinline__ void load_stage(
    uint32_t sb,
    const __half* __restrict__ Ah, const __half* __restrict__ Al,
    const __half* __restrict__ Bh, const __half* __restrict__ Bl,
    int m0, int n0, int k0, int tid)
{
    #pragma unroll
    for (int i = 0; i < 4; i++) {
        int idx = tid + i * 256;
        int r = idx >> 3, u = idx & 7;
        uint32_t doff = r * 128 + ((u ^ (r & 7)) << 4);
        size_t aoff = (size_t)(m0 + r) * C_ + k0 + u * 8;
        size_t boff = (size_t)(n0 + r) * C_ + k0 + u * 8;
        cp16(sb +         doff, Ah + aoff);
        cp16(sb + 16384 + doff, Al + aoff);
        cp16(sb + 32768 + doff, Bh + boff);
        cp16(sb + 49152 + doff, Bl + boff);
    }
}

template<int MODE>
__global__ void __launch_bounds__(256)
gemm_hmma(const __half* __restrict__ Ah, const __half* __restrict__ Al,
          const __half* __restrict__ Bh, const __half* __restrict__ Bl,
          const float* __restrict__ bias, float* __restrict__ outf,
          __half* __restrict__ outh, __half* __restrict__ outl, float scale)
{
    extern __shared__ __align__(1024) char smem[];
    uint32_t sbase = smem_u32(smem);
    const int tid  = threadIdx.x;
    const int lane = tid & 31;
    const int warp = tid >> 5;
    const int wm   = warp >> 2;
    const int wn   = warp & 3;
    const int m0   = blockIdx.y * 128;
    const int n0   = blockIdx.x * 128;

    float acc[4][4][4];
    #pragma unroll
    for (int i = 0; i < 4; i++)
        #pragma unroll
        for (int j = 0; j < 4; j++)
            #pragma unroll
            for (int k = 0; k < 4; k++) acc[i][j][k] = 0.f;

    load_stage(sbase, Ah, Al, Bh, Bl, m0, n0, 0, tid);
    CP_COMMIT();

    for (int kt = 0; kt < 16; kt++) {
        if (kt + 1 < 16) {
            load_stage(sbase + ((kt + 1) & 1) * 65536, Ah, Al, Bh, Bl,
                       m0, n0, (kt + 1) * 64, tid);
            CP_COMMIT();
            CP_WAIT(1);
        } else {
            CP_WAIT(0);
        }
        __syncthreads();

        uint32_t sb = sbase + (kt & 1) * 65536;

        #pragma unroll
        for (int ks = 0; ks < 4; ks++) {
            uint32_t ah[4][4], al[4][4];
            {
                int arow = wm * 64 + (lane & 15);
                int aku  = ks * 2 + (lane >> 4);
                #pragma unroll
                for (int mi = 0; mi < 4; mi++) {
                    int r = arow + mi * 16;
                    uint32_t addr = sb + r * 128 + ((aku ^ (r & 7)) << 4);
                    LDMX4(ah[mi], addr);
                    LDMX4(al[mi], addr + 16384);
                }
            }
            uint32_t bhf[4][2], blf[4][2];
            {
                int brow0 = wn * 32 + ((lane >> 4) << 3) + (lane & 7);
                int bku   = ks * 2 + ((lane >> 3) & 1);
                #pragma unroll
                for (int nj2 = 0; nj2 < 2; nj2++) {
                    int r = brow0 + nj2 * 16;
                    uint32_t addr = sb + 32768 + r * 128 + ((bku ^ (r & 7)) << 4);
                    uint32_t t[4];
                    LDMX4(t, addr);
                    bhf[2*nj2][0] = t[0]; bhf[2*nj2][1] = t[1];
                    bhf[2*nj2+1][0] = t[2]; bhf[2*nj2+1][1] = t[3];
                    LDMX4(t, addr + 16384);
                    blf[2*nj2][0] = t[0]; blf[2*nj2][1] = t[1];
                    blf[2*nj2+1][0] = t[2]; blf[2*nj2+1][1] = t[3];
                }
            }
            #pragma unroll
            for (int mi = 0; mi < 4; mi++)
                #pragma unroll
                for (int nj = 0; nj < 4; nj++) {
                    MMA16816(acc[mi][nj], ah[mi], bhf[nj]);
                    MMA16816(acc[mi][nj], al[mi], bhf[nj]);
                    MMA16816(acc[mi][nj], ah[mi], blf[nj]);
                }
        }
        __syncthreads();
    }

    const int r0 = lane >> 2;
    const int c0 = (lane & 3) * 2;
    #pragma unroll
    for (int mi = 0; mi < 4; mi++) {
        #pragma unroll
        for (int nj = 0; nj < 4; nj++) {
            int n = n0 + wn * 32 + nj * 8 + c0;
            float2 bv = *(const float2*)(bias + n);
            #pragma unroll
            for (int h2 = 0; h2 < 2; h2++) {
                int m = m0 + wm * 64 + mi * 16 + r0 + h2 * 8;
                float v0 = acc[mi][nj][h2*2+0] + bv.x;
                float v1 = acc[mi][nj][h2*2+1] + bv.y;
                if (MODE == 0) {
                    float2 o = {v0, v1};
                    *(float2*)(outf + (size_t)m * C_ + n) = o;
                } else {
                    v0 *= scale; v1 *= scale;
                    __half2 hh = __floats2half2_rn(v0, v1);
                    float2 hf = __half22float2(hh);
                    __half2 ll = __floats2half2_rn(v0 - hf.x, v1 - hf.y);
                    int b = m >> 11, t = m & (T_ - 1);
                    int h = n >> 6,  d = n & 63;
                    size_t idx = (((size_t)(b * H_ + h)) * T_ + t) * HD_ + d;
                    *(__half2*)(outh + idx) = hh;
                    *(__half2*)(outl + idx) = ll;
                }
            }
        }
    }
}

// ---------------------------------------------------------------------------
// Tensor-core flash attention.
// CTA: 128 q-rows (8 warps x 16), k-blocks of 128. Split-fp16 3-term MMAs.
// Q pre-scaled by 0.125*log2(e) at projection epilogue -> softmax via ex2.
// smem: Qh 16K | Ql 16K | 2 stages x (Kh,Kl,Vh,Vl 16K each) = 160 KB.
// ---------------------------------------------------------------------------
#define AT_SMEM (32768 + 2*65536)

__global__ void __launch_bounds__(256) attn_tc()
{
    extern __shared__ __align__(1024) char smem[];
    uint32_t sb = smem_u32(smem);
    const int tid  = threadIdx.x;
    const int lane = tid & 31;
    const int warp = tid >> 5;
    const int qb   = (int)gridDim.x - 1 - (int)blockIdx.x;  // heavy first
    const int bh   = blockIdx.y;

    const __half* qhp = g_qh + ((size_t)bh * T_ + qb * 128) * HD_;
    const __half* qlp = g_ql + ((size_t)bh * T_ + qb * 128) * HD_;
    const __half* khp = g_kh + (size_t)bh * T_ * HD_;
    const __half* klp = g_kl + (size_t)bh * T_ * HD_;
    const __half* vhp = g_vh + (size_t)bh * T_ * HD_;
    const __half* vlp = g_vl + (size_t)bh * T_ * HD_;

    // ---- load Q (hi+lo) into smem ----
    #pragma unroll
    for (int i = 0; i < 8; i++) {
        int idx = tid + i * 256;                 // 0..2047
        int half_sel = idx >> 10;                // 0: hi, 1: lo
        int w = idx & 1023;
        int r = w >> 3, u = w & 7;
        uint32_t doff = (half_sel ? 16384u : 0u) + r * 128 + ((u ^ (r & 7)) << 4);
        const __half* src = (half_sel ? qlp : qhp) + (size_t)r * HD_ + u * 8;
        cp16(sb + doff, src);
    }
    CP_COMMIT();

    // ---- prefetch K/V stage 0 ----
    auto load_kv = [&](int stage, int kb) {
        uint32_t st = sb + 32768 + stage * 65536;
        #pragma unroll
        for (int i = 0; i < 16; i++) {
            int idx = tid + i * 256;             // 0..4095
            int a = idx >> 10;                   // 0:Kh 1:Kl 2:Vh 3:Vl
            int w = idx & 1023;
            int r = w >> 3, u = w & 7;
            const __half* src;
            switch (a) {
                case 0: src = khp; break;
                case 1: src = klp; break;
                case 2: src = vhp; break;
                default: src = vlp; break;
            }
            src += ((size_t)(kb * 128 + r)) * HD_ + u * 8;
            cp16(st + a * 16384 + r * 128 + ((u ^ (r & 7)) << 4), src);
        }
    };
    load_kv(0, 0);
    CP_COMMIT();

    // ---- wait for Q, load Q fragments ----
    CP_WAIT(1);
    __syncthreads();
    uint32_t qfh[4][4], qfl[4][4];
    {
        int arow = warp * 16 + (lane & 15);
        #pragma unroll
        for (int ks = 0; ks < 4; ks++) {
            int u = ks * 2 + (lane >> 4);
            uint32_t addr = sb + arow * 128 + ((u ^ (arow & 7)) << 4);
            LDMX4(qfh[ks], addr);
            LDMX4(qfl[ks], addr + 16384);
        }
    }

    float o[8][4];
    #pragma unroll
    for (int j = 0; j < 8; j++)
        #pragma unroll
        for (int e = 0; e < 4; e++) o[j][e] = 0.f;
    float mrow[2] = {-1e30f, -1e30f};
    float lrow[2] = {0.f, 0.f};

    for (int kb = 0; kb <= qb; kb++) {
        if (kb < qb) { load_kv((kb + 1) & 1, kb + 1); CP_COMMIT(); CP_WAIT(1); }
        else        { CP_WAIT(0); }
        __syncthreads();

        uint32_t st = sb + 32768 + (kb & 1) * 65536;   // Kh
        uint32_t sv = st + 32768;                      // Vh

        // ---- S = Q K^T (3-term split) ----
        float s[16][4];
        #pragma unroll
        for (int j = 0; j < 16; j++)
            #pragma unroll
            for (int e = 0; e < 4; e++) s[j][e] = 0.f;

        #pragma unroll
        for (int ks = 0; ks < 4; ks++) {
            #pragma unroll
            for (int g = 0; g < 8; g++) {
                int brow = g * 16 + ((lane >> 4) << 3) + (lane & 7);
                int bku  = ks * 2 + ((lane >> 3) & 1);
                uint32_t addr = st + brow * 128 + ((bku ^ (brow & 7)) << 4);
                uint32_t kh4[4], kl4[4];
                LDMX4(kh4, addr);
                LDMX4(kl4, addr + 16384);
                MMA16816(s[2*g],   qfh[ks], kh4);
                MMA16816(s[2*g],   qfl[ks], kh4);
                MMA16816(s[2*g],   qfh[ks], kl4);
                MMA16816(s[2*g+1], qfh[ks], kh4 + 2);
                MMA16816(s[2*g+1], qfl[ks], kh4 + 2);
                MMA16816(s[2*g+1], qfh[ks], kl4 + 2);
            }
        }

        // ---- causal mask (diagonal block only) ----
        if (kb == qb) {
            int rbase = warp * 16 + (lane >> 2);
            int cbase = 2 * (lane & 3);
            #pragma unroll
            for (int j = 0; j < 16; j++) {
                int c = 8 * j + cbase;
                if (c     > rbase)     s[j][0] = -1e30f;
                if (c + 1 > rbase)     s[j][1] = -1e30f;
                if (c     > rbase + 8) s[j][2] = -1e30f;
                if (c + 1 > rbase + 8) s[j][3] = -1e30f;
            }
        }

        // ---- online softmax (base-2 domain; scale folded into Q) ----
        float mloc0 = -1e30f, mloc1 = -1e30f;
        #pragma unroll
        for (int j = 0; j < 16; j++) {
            mloc0 = fmaxf(mloc0, fmaxf(s[j][0], s[j][1]));
            mloc1 = fmaxf(mloc1, fmaxf(s[j][2], s[j][3]));
        }
        #pragma unroll
        for (int off = 1; off < 4; off <<= 1) {
            mloc0 = fmaxf(mloc0, __shfl_xor_sync(0xffffffffu, mloc0, off));
            mloc1 = fmaxf(mloc1, __shfl_xor_sync(0xffffffffu, mloc1, off));
        }
        float mn0 = fmaxf(mrow[0], mloc0);
        float mn1 = fmaxf(mrow[1], mloc1);
        float cr0 = ex2(mrow[0] - mn0);
        float cr1 = ex2(mrow[1] - mn1);
        mrow[0] = mn0; mrow[1] = mn1;

        float sum0 = 0.f, sum1 = 0.f;
        #pragma unroll
        for (int j = 0; j < 16; j++) {
            s[j][0] = ex2(s[j][0] - mn0); sum0 += s[j][0];
            s[j][1] = ex2(s[j][1] - mn0); sum0 += s[j][1];
            s[j][2] = ex2(s[j][2] - mn1); sum1 += s[j][2];
            s[j][3] = ex2(s[j][3] - mn1); sum1 += s[j][3];
        }
        #pragma unroll
        for (int off = 1; off < 4; off <<= 1) {
            sum0 += __shfl_xor_sync(0xffffffffu, sum0, off);
            sum1 += __shfl_xor_sync(0xffffffffu, sum1, off);
        }
        lrow[0] = lrow[0] * cr0 + sum0;
        lrow[1] = lrow[1] * cr1 + sum1;

        #pragma unroll
        for (int j = 0; j < 8; j++) {
            o[j][0] *= cr0; o[j][1] *= cr0;
            o[j][2] *= cr1; o[j][3] *= cr1;
        }

        // ---- O += P V (3-term split) ----
        #pragma unroll
        for (int kk = 0; kk < 8; kk++) {
            uint32_t ph[4], pl[4];
            ph[0] = packh2(s[2*kk][0],   s[2*kk][1]);
            ph[1] = packh2(s[2*kk][2],   s[2*kk][3]);
            ph[2] = packh2(s[2*kk+1][0], s[2*kk+1][1]);
            ph[3] = packh2(s[2*kk+1][2], s[2*kk+1][3]);
            #pragma unroll
            for (int e = 0; e < 4; e++) {
                float2 f = __half22float2(*reinterpret_cast<__half2*>(&ph[e]));
                int j = 2*kk + (e >> 1);
                int base = (e & 1) * 2;
                pl[e] = packh2(s[j][base] - f.x, s[j][base+1] - f.y);
            }
            int vrow = kk * 16 + ((lane >> 3) & 1) * 8 + (lane & 7);
            #pragma unroll
            for (int g = 0; g < 4; g++) {
                int vu = 2 * g + (lane >> 4);
                uint32_t addr = sv + vrow * 128 + ((vu ^ (vrow & 7)) << 4);
                uint32_t vh4[4], vl4[4];
                LDMX4T(vh4, addr);
                LDMX4T(vl4, addr + 16384);
                MMA16816(o[2*g],   ph, vh4);
                MMA16816(o[2*g],   pl, vh4);
                MMA16816(o[2*g],   ph, vl4);
                MMA16816(o[2*g+1], ph, vh4 + 2);
                MMA16816(o[2*g+1], pl, vh4 + 2);
                MMA16816(o[2*g+1], ph, vl4 + 2);
            }
        }
        __syncthreads();
    }

    // ---- epilogue: y = O / l, write hi/lo halves into out-proj input ----
    float inv0 = 1.0f / lrow[0];
    float inv1 = 1.0f / lrow[1];
    int b = bh >> 4;
    int h = bh & 15;
    int t0 = qb * 128 + warp * 16 + (lane >> 2);
    int d0 = 2 * (lane & 3);
    #pragma unroll
    for (int j = 0; j < 8; j++) {
        int d = 8 * j + d0;
        {
            float y0 = o[j][0] * inv0, y1 = o[j][1] * inv0;
            __half2 hh = __floats2half2_rn(y0, y1);
            float2 hf = __half22float2(hh);
            __half2 ll = __floats2half2_rn(y0 - hf.x, y1 - hf.y);
            size_t idx = ((size_t)(b * T_ + t0)) * C_ + h * HD_ + d;
            *(__half2*)(g_xh + idx) = hh;
            *(__half2*)(g_xl + idx) = ll;
        }
        {
            float y0 = o[j][2] * inv1, y1 = o[j][3] * inv1;
            __half2 hh = __floats2half2_rn(y0, y1);
            float2 hf = __half22float2(hh);
            __half2 ll = __floats2half2_rn(y0 - hf.x, y1 - hf.y);
            size_t idx = ((size_t)(b * T_ + t0 + 8)) * C_ + h * HD_ + d;
            *(__half2*)(g_xh + idx) = hh;
            *(__half2*)(g_xl + idx) = ll;
        }
    }
}

// ---------------------------------------------------------------------------
extern "C" void kernel_launch(void* const* d_in, const int* in_sizes, int n_in,
                              void* d_out, int out_size)
{
    const float* x  = (const float*)d_in[0];
    const float* Wq = (const float*)d_in[1];
    const float* bq = (const float*)d_in[2];
    const float* Wk = (const float*)d_in[3];
    const float* bk = (const float*)d_in[4];
    const float* Wv = (const float*)d_in[5];
    const float* bv = (const float*)d_in[6];
    const float* Wp = (const float*)d_in[7];
    const float* bp = (const float*)d_in[8];
    float* out = (float*)d_out;

    __half *qh, *ql, *kh, *kl, *vh, *vl, *xh, *xl, *wh, *wl;
    cudaGetSymbolAddress((void**)&qh, g_qh);
    cudaGetSymbolAddress((void**)&ql, g_ql);
    cudaGetSymbolAddress((void**)&kh, g_kh);
    cudaGetSymbolAddress((void**)&kl, g_kl);
    cudaGetSymbolAddress((void**)&vh, g_vh);
    cudaGetSymbolAddress((void**)&vl, g_vl);
    cudaGetSymbolAddress((void**)&xh, g_xh);
    cudaGetSymbolAddress((void**)&xl, g_xl);
    cudaGetSymbolAddress((void**)&wh, g_wh);
    cudaGetSymbolAddress((void**)&wl, g_wl);

    cudaFuncSetAttribute(gemm_hmma<0>, cudaFuncAttributeMaxDynamicSharedMemorySize, GEMM_SMEM);
    cudaFuncSetAttribute(gemm_hmma<1>, cudaFuncAttributeMaxDynamicSharedMemorySize, GEMM_SMEM);
    cudaFuncSetAttribute(attn_tc, cudaFuncAttributeMaxDynamicSharedMemorySize, AT_SMEM);

    const int NX4 = NTOK * C_ / 4;
    const int NW4 = C_ * C_ / 4;
    cvt_split<<<(NX4 + 255)/256, 256>>>((const float4*)x,  (__half2*)xh, (__half2*)xl, NX4);
    cvt_split<<<(NW4 + 255)/256, 256>>>((const float4*)Wq, (__half2*)(wh + 0*(size_t)C_*C_), (__half2*)(wl + 0*(size_t)C_*C_), NW4);
    cvt_split<<<(NW4 + 255)/256, 256>>>((const float4*)Wk, (__half2*)(wh + 1*(size_t)C_*C_), (__half2*)(wl + 1*(size_t)C_*C_), NW4);
    cvt_split<<<(NW4 + 255)/256, 256>>>((const float4*)Wv, (__half2*)(wh + 2*(size_t)C_*C_), (__half2*)(wl + 2*(size_t)C_*C_), NW4);
    cvt_split<<<(NW4 + 255)/256, 256>>>((const float4*)Wp, (__half2*)(wh + 3*(size_t)C_*C_), (__half2*)(wl + 3*(size_t)C_*C_), NW4);

    const float QSCALE = 0.125f * 1.44269504088896f;   // 1/sqrt(64) * log2(e)
    dim3 ggrid(C_/128, NTOK/128);
    gemm_hmma<1><<<ggrid, 256, GEMM_SMEM>>>(xh, xl, wh + 0*(size_t)C_*C_, wl + 0*(size_t)C_*C_, bq, nullptr, qh, ql, QSCALE);
    gemm_hmma<1><<<ggrid, 256, GEMM_SMEM>>>(xh, xl, wh + 1*(size_t)C_*C_, wl + 1*(size_t)C_*C_, bk, nullptr, kh, kl, 1.0f);
    gemm_hmma<1><<<ggrid, 256, GEMM_SMEM>>>(xh, xl, wh + 2*(size_t)C_*C_, wl + 2*(size_t)C_*C_, bv, nullptr, vh, vl, 1.0f);

    attn_tc<<<dim3(T_/128, B_*H_), 256, AT_SMEM>>>();   // writes yh/yl into xh/xl

    gemm_hmma<0><<<ggrid, 256, GEMM_SMEM>>>(xh, xl, wh + 3*(size_t)C_*C_, wl + 3*(size_t)C_*C_, bp, out, nullptr, nullptr, 1.0f);
}

// round 5
// speedup vs baseline: 3.4852x; 1.0303x over previous
#include <cuda_runtime.h>
#include <cuda_fp16.h>
#include <math.h>
#include <stdint.h>

#define B_   2
#define T_   2048
#define C_   1024
#define H_   16
#define HD_  64
#define NTOK (B_*T_)   // 4096

// ---------------------------------------------------------------------------
// Scratch (__device__ globals; allocation-free rule)
// ---------------------------------------------------------------------------
__device__ __half g_qh[NTOK*C_], g_ql[NTOK*C_];
__device__ __half g_kh[NTOK*C_], g_kl[NTOK*C_];
__device__ __half g_vh[NTOK*C_], g_vl[NTOK*C_];
__device__ __half g_xh[NTOK*C_], g_xl[NTOK*C_];   // x hi/lo, later y hi/lo
__device__ __half g_wh[4*C_*C_], g_wl[4*C_*C_];   // Wq|Wk|Wv|Wp hi/lo

// ---------------------------------------------------------------------------
// PTX helpers (sm_80-baseline only — harness compiles for sm_103 w/o 'a')
// ---------------------------------------------------------------------------
__device__ __forceinline__ uint32_t smem_u32(const void* p) {
    uint32_t a;
    asm("{ .reg .u64 t; cvta.to.shared.u64 t, %1; cvt.u32.u64 %0, t; }"
        : "=r"(a) : "l"(p));
    return a;
}
__device__ __forceinline__ void cp16(uint32_t dst, const void* src) {
    asm volatile("cp.async.ca.shared.global [%0], [%1], 16;" :: "r"(dst), "l"(src));
}
#define CP_COMMIT()  asm volatile("cp.async.commit_group;" ::: "memory")
#define CP_WAIT(N)   asm volatile("cp.async.wait_group " #N ";" ::: "memory")

#define LDMX4(r, addr) \
    asm volatile("ldmatrix.sync.aligned.m8n8.x4.shared.b16 {%0,%1,%2,%3}, [%4];" \
        : "=r"((r)[0]), "=r"((r)[1]), "=r"((r)[2]), "=r"((r)[3]) : "r"(addr))
#define LDMX4T(r, addr) \
    asm volatile("ldmatrix.sync.aligned.m8n8.x4.trans.shared.b16 {%0,%1,%2,%3}, [%4];" \
        : "=r"((r)[0]), "=r"((r)[1]), "=r"((r)[2]), "=r"((r)[3]) : "r"(addr))

#define MMA16816(d, a, b) \
    asm volatile("mma.sync.aligned.m16n8k16.row.col.f32.f16.f16.f32 " \
        "{%0,%1,%2,%3}, {%4,%5,%6,%7}, {%8,%9}, {%0,%1,%2,%3};" \
        : "+f"((d)[0]), "+f"((d)[1]), "+f"((d)[2]), "+f"((d)[3]) \
        : "r"((a)[0]), "r"((a)[1]), "r"((a)[2]), "r"((a)[3]), \
          "r"((b)[0]), "r"((b)[1]))

__device__ __forceinline__ float ex2(float x) {
    float r;
    asm("ex2.approx.ftz.f32 %0, %1;" : "=f"(r) : "f"(x));
    return r;
}
__device__ __forceinline__ uint32_t packh2(float a, float b) {
    __half2 h = __floats2half2_rn(a, b);
    return *reinterpret_cast<uint32_t*>(&h);
}

// ---------------------------------------------------------------------------
// fp32 -> (hi, lo) fp16 split conversions
// ---------------------------------------------------------------------------
__global__ void __launch_bounds__(256)
cvt_split(const float4* __restrict__ src, __half2* __restrict__ hi,
          __half2* __restrict__ lo, int n4)
{
    int i = blockIdx.x * blockDim.x + threadIdx.x;
    if (i >= n4) return;
    float4 f = src[i];
    __half2 h01 = __floats2half2_rn(f.x, f.y);
    __half2 h23 = __floats2half2_rn(f.z, f.w);
    float2 b01 = __half22float2(h01);
    float2 b23 = __half22float2(h23);
    hi[2*i]   = h01;  hi[2*i+1] = h23;
    lo[2*i]   = __floats2half2_rn(f.x - b01.x, f.y - b01.y);
    lo[2*i+1] = __floats2half2_rn(f.z - b23.x, f.w - b23.y);
}

// all 4 weight matrices in one launch; dst hi/lo are the contiguous g_wh/g_wl
__global__ void __launch_bounds__(256)
cvt_split_w4(const float4* __restrict__ s0, const float4* __restrict__ s1,
             const float4* __restrict__ s2, const float4* __restrict__ s3,
             __half2* __restrict__ hi, __half2* __restrict__ lo)
{
    const int NW4 = C_ * C_ / 4;   // 262144 = 2^18
    int i = blockIdx.x * blockDim.x + threadIdx.x;
    if (i >= 4 * NW4) return;
    int mid = i >> 18;
    int off = i & (NW4 - 1);
    const float4* src = (mid == 0) ? s0 : (mid == 1) ? s1 : (mid == 2) ? s2 : s3;
    float4 f = src[off];
    __half2 h01 = __floats2half2_rn(f.x, f.y);
    __half2 h23 = __floats2half2_rn(f.z, f.w);
    float2 b01 = __half22float2(h01);
    float2 b23 = __half22float2(h23);
    hi[2*i]   = h01;  hi[2*i+1] = h23;
    lo[2*i]   = __floats2half2_rn(f.x - b01.x, f.y - b01.y);
    lo[2*i+1] = __floats2half2_rn(f.z - b23.x, f.w - b23.y);
}

// ---------------------------------------------------------------------------
// HMMA GEMM, split-fp16 3-term. CTA tile 128x128, BK=64, 2-stage cp.async.
// MODE 0: fp32 out [m][n] (out-projection: bias b0, output outf).
// MODE 1: merged QKV — grid.x spans N=3072; matrix id = n0>>10 selects
//         bias / scale / hi-lo output pair; out layout [B,H,T,64].
// ---------------------------------------------------------------------------
#define GEMM_SMEM (2*65536)

__device__ __forceinline__ void load_stage(
    uint32_t sb,
    const __half* __restrict__ Ah, const __half* __restrict__ Al,
    const __half* __restrict__ Bh, const __half* __restrict__ Bl,
    int m0, int n0, int k0, int tid)
{
    #pragma unroll
    for (int i = 0; i < 4; i++) {
        int idx = tid + i * 256;
        int r = idx >> 3, u = idx & 7;
        uint32_t doff = r * 128 + ((u ^ (r & 7)) << 4);
        size_t aoff = (size_t)(m0 + r) * C_ + k0 + u * 8;
        size_t boff = (size_t)(n0 + r) * C_ + k0 + u * 8;
        cp16(sb +         doff, Ah + aoff);
        cp16(sb + 16384 + doff, Al + aoff);
        cp16(sb + 32768 + doff, Bh + boff);
        cp16(sb + 49152 + doff, Bl + boff);
    }
}

template<int MODE>
__global__ void __launch_bounds__(256)
gemm_hmma(const __half* __restrict__ Ah, const __half* __restrict__ Al,
          const __half* __restrict__ Bh, const __half* __restrict__ Bl,
          const float* __restrict__ b0, const float* __restrict__ b1,
          const float* __restrict__ b2,
          float* __restrict__ outf,
          __half* __restrict__ o0h, __half* __restrict__ o0l,
          __half* __restrict__ o1h, __half* __restrict__ o1l,
          __half* __restrict__ o2h, __half* __restrict__ o2l,
          float scale0)
{
    extern __shared__ __align__(1024) char smem[];
    uint32_t sbase = smem_u32(smem);
    const int tid  = threadIdx.x;
    const int lane = tid & 31;
    const int warp = tid >> 5;
    const int wm   = warp >> 2;
    const int wn   = warp & 3;
    const int m0   = blockIdx.y * 128;
    const int n0   = blockIdx.x * 128;

    float acc[4][4][4];
    #pragma unroll
    for (int i = 0; i < 4; i++)
        #pragma unroll
        for (int j = 0; j < 4; j++)
            #pragma unroll
            for (int k = 0; k < 4; k++) acc[i][j][k] = 0.f;

    load_stage(sbase, Ah, Al, Bh, Bl, m0, n0, 0, tid);
    CP_COMMIT();

    for (int kt = 0; kt < 16; kt++) {
        if (kt + 1 < 16) {
            load_stage(sbase + ((kt + 1) & 1) * 65536, Ah, Al, Bh, Bl,
                       m0, n0, (kt + 1) * 64, tid);
            CP_COMMIT();
            CP_WAIT(1);
        } else {
            CP_WAIT(0);
        }
        __syncthreads();

        uint32_t sb = sbase + (kt & 1) * 65536;

        #pragma unroll
        for (int ks = 0; ks < 4; ks++) {
            uint32_t ah[4][4], al[4][4];
            {
                int arow = wm * 64 + (lane & 15);
                int aku  = ks * 2 + (lane >> 4);
                #pragma unroll
                for (int mi = 0; mi < 4; mi++) {
                    int r = arow + mi * 16;
                    uint32_t addr = sb + r * 128 + ((aku ^ (r & 7)) << 4);
                    LDMX4(ah[mi], addr);
                    LDMX4(al[mi], addr + 16384);
                }
            }
            uint32_t bhf[4][2], blf[4][2];
            {
                int brow0 = wn * 32 + ((lane >> 4) << 3) + (lane & 7);
                int bku   = ks * 2 + ((lane >> 3) & 1);
                #pragma unroll
                for (int nj2 = 0; nj2 < 2; nj2++) {
                    int r = brow0 + nj2 * 16;
                    uint32_t addr = sb + 32768 + r * 128 + ((bku ^ (r & 7)) << 4);
                    uint32_t t[4];
                    LDMX4(t, addr);
                    bhf[2*nj2][0] = t[0]; bhf[2*nj2][1] = t[1];
                    bhf[2*nj2+1][0] = t[2]; bhf[2*nj2+1][1] = t[3];
                    LDMX4(t, addr + 16384);
                    blf[2*nj2][0] = t[0]; blf[2*nj2][1] = t[1];
                    blf[2*nj2+1][0] = t[2]; blf[2*nj2+1][1] = t[3];
                }
            }
            #pragma unroll
            for (int mi = 0; mi < 4; mi++)
                #pragma unroll
                for (int nj = 0; nj < 4; nj++) {
                    MMA16816(acc[mi][nj], ah[mi], bhf[nj]);
                    MMA16816(acc[mi][nj], al[mi], bhf[nj]);
                    MMA16816(acc[mi][nj], ah[mi], blf[nj]);
                }
        }
        __syncthreads();
    }

    // ---- epilogue ----
    const int r0 = lane >> 2;
    const int c0 = (lane & 3) * 2;

    const float* bias;
    __half *oh, *ol;
    float scale = 1.0f;
    if (MODE == 1) {
        int mid = n0 >> 10;
        bias = (mid == 0) ? b0 : (mid == 1) ? b1 : b2;
        oh   = (mid == 0) ? o0h : (mid == 1) ? o1h : o2h;
        ol   = (mid == 0) ? o0l : (mid == 1) ? o1l : o2l;
        if (mid == 0) scale = scale0;
    } else {
        bias = b0;
    }

    #pragma unroll
    for (int mi = 0; mi < 4; mi++) {
        #pragma unroll
        for (int nj = 0; nj < 4; nj++) {
            int nl = (n0 & 1023) + wn * 32 + nj * 8 + c0;
            float2 bv = *(const float2*)(bias + nl);
            #pragma unroll
            for (int h2 = 0; h2 < 2; h2++) {
                int m = m0 + wm * 64 + mi * 16 + r0 + h2 * 8;
                float v0 = acc[mi][nj][h2*2+0] + bv.x;
                float v1 = acc[mi][nj][h2*2+1] + bv.y;
                if (MODE == 0) {
                    float2 o = {v0, v1};
                    *(float2*)(outf + (size_t)m * C_ + nl) = o;
                } else {
                    v0 *= scale; v1 *= scale;
                    __half2 hh = __floats2half2_rn(v0, v1);
                    float2 hf = __half22float2(hh);
                    __half2 ll = __floats2half2_rn(v0 - hf.x, v1 - hf.y);
                    int b = m >> 11, t = m & (T_ - 1);
                    int h = nl >> 6, d = nl & 63;
                    size_t idx = (((size_t)(b * H_ + h)) * T_ + t) * HD_ + d;
                    *(__half2*)(oh + idx) = hh;
                    *(__half2*)(ol + idx) = ll;
                }
            }
        }
    }
}

// ---------------------------------------------------------------------------
// Tensor-core flash attention (split-fp16 3-term), with diagonal-block skips.
// CTA: 128 q-rows (8 warps x 16 rows), 128-key blocks, 2-stage cp.async K/V.
// ---------------------------------------------------------------------------
#define AT_SMEM (32768 + 2*65536)

__global__ void __launch_bounds__(256) attn_tc()
{
    extern __shared__ __align__(1024) char smem[];
    uint32_t sb = smem_u32(smem);
    const int tid  = threadIdx.x;
    const int lane = tid & 31;
    const int warp = tid >> 5;
    const int qb   = (int)gridDim.x - 1 - (int)blockIdx.x;  // heavy first
    const int bh   = blockIdx.y;

    const __half* qhp = g_qh + ((size_t)bh * T_ + qb * 128) * HD_;
    const __half* qlp = g_ql + ((size_t)bh * T_ + qb * 128) * HD_;
    const __half* khp = g_kh + (size_t)bh * T_ * HD_;
    const __half* klp = g_kl + (size_t)bh * T_ * HD_;
    const __half* vhp = g_vh + (size_t)bh * T_ * HD_;
    const __half* vlp = g_vl + (size_t)bh * T_ * HD_;

    #pragma unroll
    for (int i = 0; i < 8; i++) {
        int idx = tid + i * 256;
        int half_sel = idx >> 10;
        int w = idx & 1023;
        int r = w >> 3, u = w & 7;
        uint32_t doff = (half_sel ? 16384u : 0u) + r * 128 + ((u ^ (r & 7)) << 4);
        const __half* src = (half_sel ? qlp : qhp) + (size_t)r * HD_ + u * 8;
        cp16(sb + doff, src);
    }
    CP_COMMIT();

    auto load_kv = [&](int stage, int kb) {
        uint32_t st = sb + 32768 + stage * 65536;
        #pragma unroll
        for (int i = 0; i < 16; i++) {
            int idx = tid + i * 256;
            int a = idx >> 10;
            int w = idx & 1023;
            int r = w >> 3, u = w & 7;
            const __half* src;
            switch (a) {
                case 0: src = khp; break;
                case 1: src = klp; break;
                case 2: src = vhp; break;
                default: src = vlp; break;
            }
            src += ((size_t)(kb * 128 + r)) * HD_ + u * 8;
            cp16(st + a * 16384 + r * 128 + ((u ^ (r & 7)) << 4), src);
        }
    };
    load_kv(0, 0);
    CP_COMMIT();

    CP_WAIT(1);
    __syncthreads();
    uint32_t qfh[4][4], qfl[4][4];
    {
        int arow = warp * 16 + (lane & 15);
        #pragma unroll
        for (int ks = 0; ks < 4; ks++) {
            int u = ks * 2 + (lane >> 4);
            uint32_t addr = sb + arow * 128 + ((u ^ (arow & 7)) << 4);
            LDMX4(qfh[ks], addr);
            LDMX4(qfl[ks], addr + 16384);
        }
    }

    float o[8][4];
    #pragma unroll
    for (int j = 0; j < 8; j++)
        #pragma unroll
        for (int e = 0; e < 4; e++) o[j][e] = 0.f;
    float mrow[2] = {-1e30f, -1e30f};
    float lrow[2] = {0.f, 0.f};

    for (int kb = 0; kb <= qb; kb++) {
        if (kb < qb) { load_kv((kb + 1) & 1, kb + 1); CP_COMMIT(); CP_WAIT(1); }
        else        { CP_WAIT(0); }
        __syncthreads();

        const bool diag = (kb == qb);
        uint32_t st = sb + 32768 + (kb & 1) * 65536;   // Kh
        uint32_t sv = st + 32768;                      // Vh

        // ---- S = Q K^T (3-term split); on diagonal skip fully-masked key groups
        float s[16][4];
        #pragma unroll
        for (int j = 0; j < 16; j++)
            #pragma unroll
            for (int e = 0; e < 4; e++) s[j][e] = 0.f;

        #pragma unroll
        for (int g = 0; g < 8; g++) {
            if (!diag || g <= warp) {
                int brow = g * 16 + ((lane >> 4) << 3) + (lane & 7);
                #pragma unroll
                for (int ks = 0; ks < 4; ks++) {
                    int bku  = ks * 2 + ((lane >> 3) & 1);
                    uint32_t addr = st + brow * 128 + ((bku ^ (brow & 7)) << 4);
                    uint32_t kh4[4], kl4[4];
                    LDMX4(kh4, addr);
                    LDMX4(kl4, addr + 16384);
                    MMA16816(s[2*g],   qfh[ks], kh4);
                    MMA16816(s[2*g],   qfl[ks], kh4);
                    MMA16816(s[2*g],   qfh[ks], kl4);
                    MMA16816(s[2*g+1], qfh[ks], kh4 + 2);
                    MMA16816(s[2*g+1], qfl[ks], kh4 + 2);
                    MMA16816(s[2*g+1], qfh[ks], kl4 + 2);
                }
            }
        }

        if (diag) {
            int rbase = warp * 16 + (lane >> 2);
            int cbase = 2 * (lane & 3);
            #pragma unroll
            for (int j = 0; j < 16; j++) {
                int c = 8 * j + cbase;
                if (c     > rbase)     s[j][0] = -1e30f;
                if (c + 1 > rbase)     s[j][1] = -1e30f;
                if (c     > rbase + 8) s[j][2] = -1e30f;
                if (c + 1 > rbase + 8) s[j][3] = -1e30f;
            }
        }

        // ---- online softmax (base-2; scale folded into Q) ----
        float mloc0 = -1e30f, mloc1 = -1e30f;
        #pragma unroll
        for (int j = 0; j < 16; j++) {
            mloc0 = fmaxf(mloc0, fmaxf(s[j][0], s[j][1]));
            mloc1 = fmaxf(mloc1, fmaxf(s[j][2], s[j][3]));
        }
        #pragma unroll
        for (int off = 1; off < 4; off <<= 1) {
            mloc0 = fmaxf(mloc0, __shfl_xor_sync(0xffffffffu, mloc0, off));
            mloc1 = fmaxf(mloc1, __shfl_xor_sync(0xffffffffu, mloc1, off));
        }
        float mn0 = fmaxf(mrow[0], mloc0);
        float mn1 = fmaxf(mrow[1], mloc1);
        float cr0 = ex2(mrow[0] - mn0);
        float cr1 = ex2(mrow[1] - mn1);
        mrow[0] = mn0; mrow[1] = mn1;

        float sum0 = 0.f, sum1 = 0.f;
        #pragma unroll
        for (int j = 0; j < 16; j++) {
            s[j][0] = ex2(s[j][0] - mn0); sum0 += s[j][0];
            s[j][1] = ex2(s[j][1] - mn0); sum0 += s[j][1];
            s[j][2] = ex2(s[j][2] - mn1); sum1 += s[j][2];
            s[j][3] = ex2(s[j][3] - mn1); sum1 += s[j][3];
        }
        #pragma unroll
        for (int off = 1; off < 4; off <<= 1) {
            sum0 += __shfl_xor_sync(0xffffffffu, sum0, off);
            sum1 += __shfl_xor_sync(0xffffffffu, sum1, off);
        }
        lrow[0] = lrow[0] * cr0 + sum0;
        lrow[1] = lrow[1] * cr1 + sum1;

        #pragma unroll
        for (int j = 0; j < 8; j++) {
            o[j][0] *= cr0; o[j][1] *= cr0;
            o[j][2] *= cr1; o[j][3] *= cr1;
        }

        // ---- O += P V (3-term split); skip fully-masked key groups on diagonal
        #pragma unroll
        for (int kk = 0; kk < 8; kk++) {
            if (!diag || kk <= warp) {
                uint32_t ph[4], pl[4];
                ph[0] = packh2(s[2*kk][0],   s[2*kk][1]);
                ph[1] = packh2(s[2*kk][2],   s[2*kk][3]);
                ph[2] = packh2(s[2*kk+1][0], s[2*kk+1][1]);
                ph[3] = packh2(s[2*kk+1][2], s[2*kk+1][3]);
                #pragma unroll
                for (int e = 0; e < 4; e++) {
                    float2 f = __half22float2(*reinterpret_cast<__half2*>(&ph[e]));
                    int j = 2*kk + (e >> 1);
                    int base = (e & 1) * 2;
                    pl[e] = packh2(s[j][base] - f.x, s[j][base+1] - f.y);
                }
                int vrow = kk * 16 + ((lane >> 3) & 1) * 8 + (lane & 7);
                #pragma unroll
                for (int g = 0; g < 4; g++) {
                    int vu = 2 * g + (lane >> 4);
                    uint32_t addr = sv + vrow * 128 + ((vu ^ (vrow & 7)) << 4);
                    uint32_t vh4[4], vl4[4];
                    LDMX4T(vh4, addr);
                    LDMX4T(vl4, addr + 16384);
                    MMA16816(o[2*g],   ph, vh4);
                    MMA16816(o[2*g],   pl, vh4);
                    MMA16816(o[2*g],   ph, vl4);
                    MMA16816(o[2*g+1], ph, vh4 + 2);
                    MMA16816(o[2*g+1], pl, vh4 + 2);
                    MMA16816(o[2*g+1], ph, vl4 + 2);
                }
            }
        }
        __syncthreads();
    }

    // ---- epilogue: y = O / l -> hi/lo halves into out-proj input buffers ----
    float inv0 = 1.0f / lrow[0];
    float inv1 = 1.0f / lrow[1];
    int b = bh >> 4;
    int h = bh & 15;
    int t0 = qb * 128 + warp * 16 + (lane >> 2);
    int d0 = 2 * (lane & 3);
    #pragma unroll
    for (int j = 0; j < 8; j++) {
        int d = 8 * j + d0;
        {
            float y0 = o[j][0] * inv0, y1 = o[j][1] * inv0;
            __half2 hh = __floats2half2_rn(y0, y1);
            float2 hf = __half22float2(hh);
            __half2 ll = __floats2half2_rn(y0 - hf.x, y1 - hf.y);
            size_t idx = ((size_t)(b * T_ + t0)) * C_ + h * HD_ + d;
            *(__half2*)(g_xh + idx) = hh;
            *(__half2*)(g_xl + idx) = ll;
        }
        {
            float y0 = o[j][2] * inv1, y1 = o[j][3] * inv1;
            __half2 hh = __floats2half2_rn(y0, y1);
            float2 hf = __half22float2(hh);
            __half2 ll = __floats2half2_rn(y0 - hf.x, y1 - hf.y);
            size_t idx = ((size_t)(b * T_ + t0 + 8)) * C_ + h * HD_ + d;
            *(__half2*)(g_xh + idx) = hh;
            *(__half2*)(g_xl + idx) = ll;
        }
    }
}

// ---------------------------------------------------------------------------
extern "C" void kernel_launch(void* const* d_in, const int* in_sizes, int n_in,
                              void* d_out, int out_size)
{
    const float* x  = (const float*)d_in[0];
    const float* Wq = (const float*)d_in[1];
    const float* bq = (const float*)d_in[2];
    const float* Wk = (const float*)d_in[3];
    const float* bk = (const float*)d_in[4];
    const float* Wv = (const float*)d_in[5];
    const float* bv = (const float*)d_in[6];
    const float* Wp = (const float*)d_in[7];
    const float* bp = (const float*)d_in[8];
    float* out = (float*)d_out;

    __half *qh, *ql, *kh, *kl, *vh, *vl, *xh, *xl, *wh, *wl;
    cudaGetSymbolAddress((void**)&qh, g_qh);
    cudaGetSymbolAddress((void**)&ql, g_ql);
    cudaGetSymbolAddress((void**)&kh, g_kh);
    cudaGetSymbolAddress((void**)&kl, g_kl);
    cudaGetSymbolAddress((void**)&vh, g_vh);
    cudaGetSymbolAddress((void**)&vl, g_vl);
    cudaGetSymbolAddress((void**)&xh, g_xh);
    cudaGetSymbolAddress((void**)&xl, g_xl);
    cudaGetSymbolAddress((void**)&wh, g_wh);
    cudaGetSymbolAddress((void**)&wl, g_wl);

    cudaFuncSetAttribute(gemm_hmma<0>, cudaFuncAttributeMaxDynamicSharedMemorySize, GEMM_SMEM);
    cudaFuncSetAttribute(gemm_hmma<1>, cudaFuncAttributeMaxDynamicSharedMemorySize, GEMM_SMEM);
    cudaFuncSetAttribute(attn_tc, cudaFuncAttributeMaxDynamicSharedMemorySize, AT_SMEM);

    const int NX4 = NTOK * C_ / 4;     // 1M
    const int NW4 = C_ * C_ / 4;       // 256K
    cvt_split<<<(NX4 + 255)/256, 256>>>((const float4*)x, (__half2*)xh, (__half2*)xl, NX4);
    cvt_split_w4<<<(4*NW4 + 255)/256, 256>>>(
        (const float4*)Wq, (const float4*)Wk, (const float4*)Wv, (const float4*)Wp,
        (__half2*)wh, (__half2*)wl);

    const float QSCALE = 0.125f * 1.44269504088896f;   // 1/sqrt(64) * log2(e)

    // merged QKV projection: N = 3072
    dim3 qkv_grid(3*C_/128, NTOK/128);   // (24, 32)
    gemm_hmma<1><<<qkv_grid, 256, GEMM_SMEM>>>(
        xh, xl, wh, wl, bq, bk, bv, nullptr,
        qh, ql, kh, kl, vh, vl, QSCALE);

    attn_tc<<<dim3(T_/128, B_*H_), 256, AT_SMEM>>>();   // writes y hi/lo into xh/xl

    dim3 ggrid(C_/128, NTOK/128);        // (8, 32)
    gemm_hmma<0><<<ggrid, 256, GEMM_SMEM>>>(
        xh, xl, wh + 3*(size_t)C_*C_, wl + 3*(size_t)C_*C_, bp, nullptr, nullptr,
        out, nullptr, nullptr, nullptr, nullptr, nullptr, nullptr, 1.0f);
}

// round 6
// speedup vs baseline: 3.5590x; 1.0212x over previous
#include <cuda_runtime.h>
#include <cuda_fp16.h>
#include <math.h>
#include <stdint.h>

#define B_   2
#define T_   2048
#define C_   1024
#define H_   16
#define HD_  64
#define NTOK (B_*T_)   // 4096

// ---------------------------------------------------------------------------
// Scratch (__device__ globals; allocation-free rule)
// ---------------------------------------------------------------------------
__device__ __half g_qh[NTOK*C_], g_ql[NTOK*C_];
__device__ __half g_kh[NTOK*C_], g_kl[NTOK*C_];
__device__ __half g_vh[NTOK*C_], g_vl[NTOK*C_];
__device__ __half g_xh[NTOK*C_], g_xl[NTOK*C_];   // x hi/lo, later y hi/lo
__device__ __half g_wh[4*C_*C_], g_wl[4*C_*C_];   // Wq|Wk|Wv|Wp hi/lo

// ---------------------------------------------------------------------------
// PTX helpers (sm_80-baseline only — harness compiles for sm_103 w/o 'a')
// ---------------------------------------------------------------------------
__device__ __forceinline__ uint32_t smem_u32(const void* p) {
    uint32_t a;
    asm("{ .reg .u64 t; cvta.to.shared.u64 t, %1; cvt.u32.u64 %0, t; }"
        : "=r"(a) : "l"(p));
    return a;
}
__device__ __forceinline__ void cp16(uint32_t dst, const void* src) {
    asm volatile("cp.async.ca.shared.global [%0], [%1], 16;" :: "r"(dst), "l"(src));
}
#define CP_COMMIT()  asm volatile("cp.async.commit_group;" ::: "memory")
#define CP_WAIT(N)   asm volatile("cp.async.wait_group " #N ";" ::: "memory")

#define LDMX4(r, addr) \
    asm volatile("ldmatrix.sync.aligned.m8n8.x4.shared.b16 {%0,%1,%2,%3}, [%4];" \
        : "=r"((r)[0]), "=r"((r)[1]), "=r"((r)[2]), "=r"((r)[3]) : "r"(addr))
#define LDMX4T(r, addr) \
    asm volatile("ldmatrix.sync.aligned.m8n8.x4.trans.shared.b16 {%0,%1,%2,%3}, [%4];" \
        : "=r"((r)[0]), "=r"((r)[1]), "=r"((r)[2]), "=r"((r)[3]) : "r"(addr))

#define MMA16816(d, a, b) \
    asm volatile("mma.sync.aligned.m16n8k16.row.col.f32.f16.f16.f32 " \
        "{%0,%1,%2,%3}, {%4,%5,%6,%7}, {%8,%9}, {%0,%1,%2,%3};" \
        : "+f"((d)[0]), "+f"((d)[1]), "+f"((d)[2]), "+f"((d)[3]) \
        : "r"((a)[0]), "r"((a)[1]), "r"((a)[2]), "r"((a)[3]), \
          "r"((b)[0]), "r"((b)[1]))

__device__ __forceinline__ float ex2(float x) {
    float r;
    asm("ex2.approx.ftz.f32 %0, %1;" : "=f"(r) : "f"(x));
    return r;
}
__device__ __forceinline__ uint32_t packh2(float a, float b) {
    __half2 h = __floats2half2_rn(a, b);
    return *reinterpret_cast<uint32_t*>(&h);
}

// ---------------------------------------------------------------------------
// fp32 -> (hi, lo) fp16 split conversions
// ---------------------------------------------------------------------------
__global__ void __launch_bounds__(256)
cvt_split(const float4* __restrict__ src, __half2* __restrict__ hi,
          __half2* __restrict__ lo, int n4)
{
    int i = blockIdx.x * blockDim.x + threadIdx.x;
    if (i >= n4) return;
    float4 f = src[i];
    __half2 h01 = __floats2half2_rn(f.x, f.y);
    __half2 h23 = __floats2half2_rn(f.z, f.w);
    float2 b01 = __half22float2(h01);
    float2 b23 = __half22float2(h23);
    hi[2*i]   = h01;  hi[2*i+1] = h23;
    lo[2*i]   = __floats2half2_rn(f.x - b01.x, f.y - b01.y);
    lo[2*i+1] = __floats2half2_rn(f.z - b23.x, f.w - b23.y);
}

__global__ void __launch_bounds__(256)
cvt_split_w4(const float4* __restrict__ s0, const float4* __restrict__ s1,
             const float4* __restrict__ s2, const float4* __restrict__ s3,
             __half2* __restrict__ hi, __half2* __restrict__ lo)
{
    const int NW4 = C_ * C_ / 4;   // 262144 = 2^18
    int i = blockIdx.x * blockDim.x + threadIdx.x;
    if (i >= 4 * NW4) return;
    int mid = i >> 18;
    int off = i & (NW4 - 1);
    const float4* src = (mid == 0) ? s0 : (mid == 1) ? s1 : (mid == 2) ? s2 : s3;
    float4 f = src[off];
    __half2 h01 = __floats2half2_rn(f.x, f.y);
    __half2 h23 = __floats2half2_rn(f.z, f.w);
    float2 b01 = __half22float2(h01);
    float2 b23 = __half22float2(h23);
    hi[2*i]   = h01;  hi[2*i+1] = h23;
    lo[2*i]   = __floats2half2_rn(f.x - b01.x, f.y - b01.y);
    lo[2*i+1] = __floats2half2_rn(f.z - b23.x, f.w - b23.y);
}

// ---------------------------------------------------------------------------
// HMMA GEMM, split-fp16 3-term. CTA tile 128x128, BK=64, 2-stage cp.async.
// MODE 0: fp32 out [m][n].  MODE 1: merged QKV (N=3072), head-split hi/lo out.
// ---------------------------------------------------------------------------
#define GEMM_SMEM (2*65536)

__device__ __forceinline__ void load_stage(
    uint32_t sb,
    const __half* __restrict__ Ah, const __half* __restrict__ Al,
    const __half* __restrict__ Bh, const __half* __restrict__ Bl,
    int m0, int n0, int k0, int tid)
{
    #pragma unroll
    for (int i = 0; i < 4; i++) {
        int idx = tid + i * 256;
        int r = idx >> 3, u = idx & 7;
        uint32_t doff = r * 128 + ((u ^ (r & 7)) << 4);
        size_t aoff = (size_t)(m0 + r) * C_ + k0 + u * 8;
        size_t boff = (size_t)(n0 + r) * C_ + k0 + u * 8;
        cp16(sb +         doff, Ah + aoff);
        cp16(sb + 16384 + doff, Al + aoff);
        cp16(sb + 32768 + doff, Bh + boff);
        cp16(sb + 49152 + doff, Bl + boff);
    }
}

template<int MODE>
__global__ void __launch_bounds__(256)
gemm_hmma(const __half* __restrict__ Ah, const __half* __restrict__ Al,
          const __half* __restrict__ Bh, const __half* __restrict__ Bl,
          const float* __restrict__ b0, const float* __restrict__ b1,
          const float* __restrict__ b2,
          float* __restrict__ outf,
          __half* __restrict__ o0h, __half* __restrict__ o0l,
          __half* __restrict__ o1h, __half* __restrict__ o1l,
          __half* __restrict__ o2h, __half* __restrict__ o2l,
          float scale0)
{
    extern __shared__ __align__(1024) char smem[];
    uint32_t sbase = smem_u32(smem);
    const int tid  = threadIdx.x;
    const int lane = tid & 31;
    const int warp = tid >> 5;
    const int wm   = warp >> 2;
    const int wn   = warp & 3;
    const int m0   = blockIdx.y * 128;
    const int n0   = blockIdx.x * 128;

    float acc[4][4][4];
    #pragma unroll
    for (int i = 0; i < 4; i++)
        #pragma unroll
        for (int j = 0; j < 4; j++)
            #pragma unroll
            for (int k = 0; k < 4; k++) acc[i][j][k] = 0.f;

    load_stage(sbase, Ah, Al, Bh, Bl, m0, n0, 0, tid);
    CP_COMMIT();

    for (int kt = 0; kt < 16; kt++) {
        if (kt + 1 < 16) {
            load_stage(sbase + ((kt + 1) & 1) * 65536, Ah, Al, Bh, Bl,
                       m0, n0, (kt + 1) * 64, tid);
            CP_COMMIT();
            CP_WAIT(1);
        } else {
            CP_WAIT(0);
        }
        __syncthreads();

        uint32_t sb = sbase + (kt & 1) * 65536;

        #pragma unroll
        for (int ks = 0; ks < 4; ks++) {
            uint32_t ah[4][4], al[4][4];
            {
                int arow = wm * 64 + (lane & 15);
                int aku  = ks * 2 + (lane >> 4);
                #pragma unroll
                for (int mi = 0; mi < 4; mi++) {
                    int r = arow + mi * 16;
                    uint32_t addr = sb + r * 128 + ((aku ^ (r & 7)) << 4);
                    LDMX4(ah[mi], addr);
                    LDMX4(al[mi], addr + 16384);
                }
            }
            uint32_t bhf[4][2], blf[4][2];
            {
                int brow0 = wn * 32 + ((lane >> 4) << 3) + (lane & 7);
                int bku   = ks * 2 + ((lane >> 3) & 1);
                #pragma unroll
                for (int nj2 = 0; nj2 < 2; nj2++) {
                    int r = brow0 + nj2 * 16;
                    uint32_t addr = sb + 32768 + r * 128 + ((bku ^ (r & 7)) << 4);
                    uint32_t t[4];
                    LDMX4(t, addr);
                    bhf[2*nj2][0] = t[0]; bhf[2*nj2][1] = t[1];
                    bhf[2*nj2+1][0] = t[2]; bhf[2*nj2+1][1] = t[3];
                    LDMX4(t, addr + 16384);
                    blf[2*nj2][0] = t[0]; blf[2*nj2][1] = t[1];
                    blf[2*nj2+1][0] = t[2]; blf[2*nj2+1][1] = t[3];
                }
            }
            #pragma unroll
            for (int mi = 0; mi < 4; mi++)
                #pragma unroll
                for (int nj = 0; nj < 4; nj++) {
                    MMA16816(acc[mi][nj], ah[mi], bhf[nj]);
                    MMA16816(acc[mi][nj], al[mi], bhf[nj]);
                    MMA16816(acc[mi][nj], ah[mi], blf[nj]);
                }
        }
        __syncthreads();
    }

    const int r0 = lane >> 2;
    const int c0 = (lane & 3) * 2;

    const float* bias;
    __half *oh, *ol;
    float scale = 1.0f;
    if (MODE == 1) {
        int mid = n0 >> 10;
        bias = (mid == 0) ? b0 : (mid == 1) ? b1 : b2;
        oh   = (mid == 0) ? o0h : (mid == 1) ? o1h : o2h;
        ol   = (mid == 0) ? o0l : (mid == 1) ? o1l : o2l;
        if (mid == 0) scale = scale0;
    } else {
        bias = b0;
    }

    #pragma unroll
    for (int mi = 0; mi < 4; mi++) {
        #pragma unroll
        for (int nj = 0; nj < 4; nj++) {
            int nl = (n0 & 1023) + wn * 32 + nj * 8 + c0;
            float2 bv = *(const float2*)(bias + nl);
            #pragma unroll
            for (int h2 = 0; h2 < 2; h2++) {
                int m = m0 + wm * 64 + mi * 16 + r0 + h2 * 8;
                float v0 = acc[mi][nj][h2*2+0] + bv.x;
                float v1 = acc[mi][nj][h2*2+1] + bv.y;
                if (MODE == 0) {
                    float2 o = {v0, v1};
                    *(float2*)(outf + (size_t)m * C_ + nl) = o;
                } else {
                    v0 *= scale; v1 *= scale;
                    __half2 hh = __floats2half2_rn(v0, v1);
                    float2 hf = __half22float2(hh);
                    __half2 ll = __floats2half2_rn(v0 - hf.x, v1 - hf.y);
                    int b = m >> 11, t = m & (T_ - 1);
                    int h = nl >> 6, d = nl & 63;
                    size_t idx = (((size_t)(b * H_ + h)) * T_ + t) * HD_ + d;
                    *(__half2*)(oh + idx) = hh;
                    *(__half2*)(ol + idx) = ll;
                }
            }
        }
    }
}

// ---------------------------------------------------------------------------
// Tensor-core flash attention v2: 4-warp CTAs, 64 q-rows, 64-key blocks,
// 2-stage cp.async, 80 KB smem -> 2 CTAs/SM. Split-fp16 3-term MMAs.
// smem: Qh 8K | Ql 8K | 2 stages x (Kh,Kl,Vh,Vl 8K each) = 80 KB.
// ---------------------------------------------------------------------------
#define AT_SMEM (16384 + 2*32768)

__global__ void __launch_bounds__(128, 2) attn_tc()
{
    extern __shared__ __align__(1024) char smem[];
    uint32_t sb = smem_u32(smem);
    const int tid  = threadIdx.x;
    const int lane = tid & 31;
    const int warp = tid >> 5;                              // 0..3
    const int qt   = (int)gridDim.x - 1 - (int)blockIdx.x;  // heavy first
    const int bh   = blockIdx.y;
    const int nkb  = qt + 1;                                // 64-key blocks

    const __half* qhp = g_qh + ((size_t)bh * T_ + qt * 64) * HD_;
    const __half* qlp = g_ql + ((size_t)bh * T_ + qt * 64) * HD_;
    const __half* khp = g_kh + (size_t)bh * T_ * HD_;
    const __half* klp = g_kl + (size_t)bh * T_ * HD_;
    const __half* vhp = g_vh + (size_t)bh * T_ * HD_;
    const __half* vlp = g_vl + (size_t)bh * T_ * HD_;

    // ---- load Q (hi+lo): 1024 cp16 ----
    #pragma unroll
    for (int i = 0; i < 8; i++) {
        int idx = tid + i * 128;               // 0..1023
        int half_sel = idx >> 9;               // 0: hi, 1: lo
        int w = idx & 511;
        int r = w >> 3, u = w & 7;
        uint32_t doff = half_sel * 8192u + r * 128 + ((u ^ (r & 7)) << 4);
        const __half* src = (half_sel ? qlp : qhp) + (size_t)r * HD_ + u * 8;
        cp16(sb + doff, src);
    }
    CP_COMMIT();

    // ---- K/V stage loader: 64 keys (Kh,Kl,Vh,Vl @ 8 KB each) ----
    auto load_kv = [&](int stage, int kb) {
        uint32_t st = sb + 16384 + stage * 32768;
        #pragma unroll
        for (int i = 0; i < 16; i++) {
            int idx = tid + i * 128;           // 0..2047
            int a = idx >> 9;                  // 0:Kh 1:Kl 2:Vh 3:Vl
            int w = idx & 511;
            int r = w >> 3, u = w & 7;
            const __half* src;
            switch (a) {
                case 0: src = khp; break;
                case 1: src = klp; break;
                case 2: src = vhp; break;
                default: src = vlp; break;
            }
            src += ((size_t)(kb * 64 + r)) * HD_ + u * 8;
            cp16(st + a * 8192 + r * 128 + ((u ^ (r & 7)) << 4), src);
        }
    };
    load_kv(0, 0);
    CP_COMMIT();

    // ---- wait for Q, load Q fragments ----
    CP_WAIT(1);
    __syncthreads();
    uint32_t qfh[4][4], qfl[4][4];
    {
        int arow = warp * 16 + (lane & 15);
        #pragma unroll
        for (int ks = 0; ks < 4; ks++) {
            int u = ks * 2 + (lane >> 4);
            uint32_t addr = sb + arow * 128 + ((u ^ (arow & 7)) << 4);
            LDMX4(qfh[ks], addr);
            LDMX4(qfl[ks], addr + 8192);
        }
    }

    float o[8][4];
    #pragma unroll
    for (int j = 0; j < 8; j++)
        #pragma unroll
        for (int e = 0; e < 4; e++) o[j][e] = 0.f;
    float mrow[2] = {-1e30f, -1e30f};
    float lrow[2] = {0.f, 0.f};

    for (int kb = 0; kb < nkb; kb++) {
        if (kb + 1 < nkb) { load_kv((kb + 1) & 1, kb + 1); CP_COMMIT(); CP_WAIT(1); }
        else              { CP_WAIT(0); }
        __syncthreads();

        const bool diag = (kb == nkb - 1);
        uint32_t st = sb + 16384 + (kb & 1) * 32768;   // Kh
        uint32_t sv = st + 16384;                      // Vh

        // ---- S = Q K^T (3-term split); diag: skip key groups g > warp ----
        float s[8][4];
        #pragma unroll
        for (int j = 0; j < 8; j++)
            #pragma unroll
            for (int e = 0; e < 4; e++) s[j][e] = 0.f;

        #pragma unroll
        for (int g = 0; g < 4; g++) {
            if (!diag || g <= warp) {
                int brow = g * 16 + ((lane >> 4) << 3) + (lane & 7);
                #pragma unroll
                for (int ks = 0; ks < 4; ks++) {
                    int bku  = ks * 2 + ((lane >> 3) & 1);
                    uint32_t addr = st + brow * 128 + ((bku ^ (brow & 7)) << 4);
                    uint32_t kh4[4], kl4[4];
                    LDMX4(kh4, addr);
                    LDMX4(kl4, addr + 8192);
                    MMA16816(s[2*g],   qfh[ks], kh4);
                    MMA16816(s[2*g],   qfl[ks], kh4);
                    MMA16816(s[2*g],   qfh[ks], kl4);
                    MMA16816(s[2*g+1], qfh[ks], kh4 + 2);
                    MMA16816(s[2*g+1], qfl[ks], kh4 + 2);
                    MMA16816(s[2*g+1], qfh[ks], kl4 + 2);
                }
            }
        }

        if (diag) {
            int rbase = warp * 16 + (lane >> 2);
            int cbase = 2 * (lane & 3);
            #pragma unroll
            for (int j = 0; j < 8; j++) {
                int c = 8 * j + cbase;
                if (c     > rbase)     s[j][0] = -1e30f;
                if (c + 1 > rbase)     s[j][1] = -1e30f;
                if (c     > rbase + 8) s[j][2] = -1e30f;
                if (c + 1 > rbase + 8) s[j][3] = -1e30f;
            }
        }

        // ---- online softmax (base-2; scale folded into Q) ----
        float mloc0 = -1e30f, mloc1 = -1e30f;
        #pragma unroll
        for (int j = 0; j < 8; j++) {
            mloc0 = fmaxf(mloc0, fmaxf(s[j][0], s[j][1]));
            mloc1 = fmaxf(mloc1, fmaxf(s[j][2], s[j][3]));
        }
        #pragma unroll
        for (int off = 1; off < 4; off <<= 1) {
            mloc0 = fmaxf(mloc0, __shfl_xor_sync(0xffffffffu, mloc0, off));
            mloc1 = fmaxf(mloc1, __shfl_xor_sync(0xffffffffu, mloc1, off));
        }
        float mn0 = fmaxf(mrow[0], mloc0);
        float mn1 = fmaxf(mrow[1], mloc1);
        float cr0 = ex2(mrow[0] - mn0);
        float cr1 = ex2(mrow[1] - mn1);
        mrow[0] = mn0; mrow[1] = mn1;

        float sum0 = 0.f, sum1 = 0.f;
        #pragma unroll
        for (int j = 0; j < 8; j++) {
            s[j][0] = ex2(s[j][0] - mn0); sum0 += s[j][0];
            s[j][1] = ex2(s[j][1] - mn0); sum0 += s[j][1];
            s[j][2] = ex2(s[j][2] - mn1); sum1 += s[j][2];
            s[j][3] = ex2(s[j][3] - mn1); sum1 += s[j][3];
        }
        #pragma unroll
        for (int off = 1; off < 4; off <<= 1) {
            sum0 += __shfl_xor_sync(0xffffffffu, sum0, off);
            sum1 += __shfl_xor_sync(0xffffffffu, sum1, off);
        }
        lrow[0] = lrow[0] * cr0 + sum0;
        lrow[1] = lrow[1] * cr1 + sum1;

        #pragma unroll
        for (int j = 0; j < 8; j++) {
            o[j][0] *= cr0; o[j][1] *= cr0;
            o[j][2] *= cr1; o[j][3] *= cr1;
        }

        // ---- O += P V (3-term split); diag: skip key chunks kk > warp ----
        #pragma unroll
        for (int kk = 0; kk < 4; kk++) {
            if (!diag || kk <= warp) {
                uint32_t ph[4], pl[4];
                ph[0] = packh2(s[2*kk][0],   s[2*kk][1]);
                ph[1] = packh2(s[2*kk][2],   s[2*kk][3]);
                ph[2] = packh2(s[2*kk+1][0], s[2*kk+1][1]);
                ph[3] = packh2(s[2*kk+1][2], s[2*kk+1][3]);
                #pragma unroll
                for (int e = 0; e < 4; e++) {
                    float2 f = __half22float2(*reinterpret_cast<__half2*>(&ph[e]));
                    int j = 2*kk + (e >> 1);
                    int base = (e & 1) * 2;
                    pl[e] = packh2(s[j][base] - f.x, s[j][base+1] - f.y);
                }
                int vrow = kk * 16 + ((lane >> 3) & 1) * 8 + (lane & 7);
                #pragma unroll
                for (int g = 0; g < 4; g++) {
                    int vu = 2 * g + (lane >> 4);
                    uint32_t addr = sv + vrow * 128 + ((vu ^ (vrow & 7)) << 4);
                    uint32_t vh4[4], vl4[4];
                    LDMX4T(vh4, addr);
                    LDMX4T(vl4, addr + 8192);
                    MMA16816(o[2*g],   ph, vh4);
                    MMA16816(o[2*g],   pl, vh4);
                    MMA16816(o[2*g],   ph, vl4);
                    MMA16816(o[2*g+1], ph, vh4 + 2);
                    MMA16816(o[2*g+1], pl, vh4 + 2);
                    MMA16816(o[2*g+1], ph, vl4 + 2);
                }
            }
        }
        __syncthreads();
    }

    // ---- epilogue: y = O / l -> hi/lo halves into out-proj input buffers ----
    float inv0 = 1.0f / lrow[0];
    float inv1 = 1.0f / lrow[1];
    int b = bh >> 4;
    int h = bh & 15;
    int t0 = qt * 64 + warp * 16 + (lane >> 2);
    int d0 = 2 * (lane & 3);
    #pragma unroll
    for (int j = 0; j < 8; j++) {
        int d = 8 * j + d0;
        {
            float y0 = o[j][0] * inv0, y1 = o[j][1] * inv0;
            __half2 hh = __floats2half2_rn(y0, y1);
            float2 hf = __half22float2(hh);
            __half2 ll = __floats2half2_rn(y0 - hf.x, y1 - hf.y);
            size_t idx = ((size_t)(b * T_ + t0)) * C_ + h * HD_ + d;
            *(__half2*)(g_xh + idx) = hh;
            *(__half2*)(g_xl + idx) = ll;
        }
        {
            float y0 = o[j][2] * inv1, y1 = o[j][3] * inv1;
            __half2 hh = __floats2half2_rn(y0, y1);
            float2 hf = __half22float2(hh);
            __half2 ll = __floats2half2_rn(y0 - hf.x, y1 - hf.y);
            size_t idx = ((size_t)(b * T_ + t0 + 8)) * C_ + h * HD_ + d;
            *(__half2*)(g_xh + idx) = hh;
            *(__half2*)(g_xl + idx) = ll;
        }
    }
}

// ---------------------------------------------------------------------------
extern "C" void kernel_launch(void* const* d_in, const int* in_sizes, int n_in,
                              void* d_out, int out_size)
{
    const float* x  = (const float*)d_in[0];
    const float* Wq = (const float*)d_in[1];
    const float* bq = (const float*)d_in[2];
    const float* Wk = (const float*)d_in[3];
    const float* bk = (const float*)d_in[4];
    const float* Wv = (const float*)d_in[5];
    const float* bv = (const float*)d_in[6];
    const float* Wp = (const float*)d_in[7];
    const float* bp = (const float*)d_in[8];
    float* out = (float*)d_out;

    __half *qh, *ql, *kh, *kl, *vh, *vl, *xh, *xl, *wh, *wl;
    cudaGetSymbolAddress((void**)&qh, g_qh);
    cudaGetSymbolAddress((void**)&ql, g_ql);
    cudaGetSymbolAddress((void**)&kh, g_kh);
    cudaGetSymbolAddress((void**)&kl, g_kl);
    cudaGetSymbolAddress((void**)&vh, g_vh);
    cudaGetSymbolAddress((void**)&vl, g_vl);
    cudaGetSymbolAddress((void**)&xh, g_xh);
    cudaGetSymbolAddress((void**)&xl, g_xl);
    cudaGetSymbolAddress((void**)&wh, g_wh);
    cudaGetSymbolAddress((void**)&wl, g_wl);

    cudaFuncSetAttribute(gemm_hmma<0>, cudaFuncAttributeMaxDynamicSharedMemorySize, GEMM_SMEM);
    cudaFuncSetAttribute(gemm_hmma<1>, cudaFuncAttributeMaxDynamicSharedMemorySize, GEMM_SMEM);
    cudaFuncSetAttribute(attn_tc, cudaFuncAttributeMaxDynamicSharedMemorySize, AT_SMEM);

    const int NX4 = NTOK * C_ / 4;     // 1M
    const int NW4 = C_ * C_ / 4;       // 256K
    cvt_split<<<(NX4 + 255)/256, 256>>>((const float4*)x, (__half2*)xh, (__half2*)xl, NX4);
    cvt_split_w4<<<(4*NW4 + 255)/256, 256>>>(
        (const float4*)Wq, (const float4*)Wk, (const float4*)Wv, (const float4*)Wp,
        (__half2*)wh, (__half2*)wl);

    const float QSCALE = 0.125f * 1.44269504088896f;   // 1/sqrt(64) * log2(e)

    dim3 qkv_grid(3*C_/128, NTOK/128);   // (24, 32)
    gemm_hmma<1><<<qkv_grid, 256, GEMM_SMEM>>>(
        xh, xl, wh, wl, bq, bk, bv, nullptr,
        qh, ql, kh, kl, vh, vl, QSCALE);

    attn_tc<<<dim3(T_/64, B_*H_), 128, AT_SMEM>>>();   // writes y hi/lo into xh/xl

    dim3 ggrid(C_/128, NTOK/128);        // (8, 32)
    gemm_hmma<0><<<ggrid, 256, GEMM_SMEM>>>(
        xh, xl, wh + 3*(size_t)C_*C_, wl + 3*(size_t)C_*C_, bp, nullptr, nullptr,
        out, nullptr, nullptr, nullptr, nullptr, nullptr, nullptr, 1.0f);
}